// round 7
// baseline (speedup 1.0000x reference)
#include <cuda_runtime.h>
#include <cuda_fp16.h>
#include <cstdint>

#define WINS   4096
#define NTOK   49
#define DIM    256
#define HEADS  8
#define DH     32
#define TTOT   (WINS * NTOK)      // 200704
#define QKV_E  768
#define SCALE  0.17677669529663687f

// ------------------------- scratch (device globals) -------------------------
__device__ __half g_x16 [(size_t)TTOT * DIM];     // 103 MB
__device__ __half g_wq16[QKV_E * DIM];
__device__ __half g_wo16[DIM * DIM];
__device__ __half g_qkv [(size_t)TTOT * QKV_E];   // 308 MB
__device__ float  g_biasP[HEADS * 64 * 64];       // padded bias

// ------------------------------ helpers ------------------------------------
__device__ __forceinline__ uint32_t smem_u32(const void* p) {
    uint32_t a;
    asm("{ .reg .u64 t; cvta.to.shared.u64 t, %1; cvt.u32.u64 %0, t; }"
        : "=r"(a) : "l"(p));
    return a;
}
__device__ __forceinline__ void cp16(uint32_t dst, const void* src) {
    asm volatile("cp.async.ca.shared.global [%0], [%1], 16;\n" :: "r"(dst), "l"(src));
}
__device__ __forceinline__ void cp_commit() {
    asm volatile("cp.async.commit_group;\n" ::);
}
template <int N> __device__ __forceinline__ void cp_wait() {
    asm volatile("cp.async.wait_group %0;\n" :: "n"(N) : "memory");
}
__device__ __forceinline__ void ldsm4(uint32_t& r0, uint32_t& r1, uint32_t& r2,
                                      uint32_t& r3, uint32_t a) {
    asm volatile("ldmatrix.sync.aligned.m8n8.x4.shared.b16 {%0,%1,%2,%3}, [%4];"
                 : "=r"(r0), "=r"(r1), "=r"(r2), "=r"(r3) : "r"(a) : "memory");
}
__device__ __forceinline__ void ldsm4t(uint32_t& r0, uint32_t& r1, uint32_t& r2,
                                       uint32_t& r3, uint32_t a) {
    asm volatile("ldmatrix.sync.aligned.m8n8.x4.trans.shared.b16 {%0,%1,%2,%3}, [%4];"
                 : "=r"(r0), "=r"(r1), "=r"(r2), "=r"(r3) : "r"(a) : "memory");
}
__device__ __forceinline__ void mma16816(float* d, uint32_t a0, uint32_t a1,
                                         uint32_t a2, uint32_t a3,
                                         uint32_t b0, uint32_t b1) {
    asm volatile(
        "mma.sync.aligned.m16n8k16.row.col.f32.f16.f16.f32 "
        "{%0,%1,%2,%3}, {%4,%5,%6,%7}, {%8,%9}, {%0,%1,%2,%3};"
        : "+f"(d[0]), "+f"(d[1]), "+f"(d[2]), "+f"(d[3])
        : "r"(a0), "r"(a1), "r"(a2), "r"(a3), "r"(b0), "r"(b1));
}
__device__ __forceinline__ uint32_t f22h2(float lo, float hi) {
    uint32_t r;
    asm("cvt.rn.f16x2.f32 %0, %1, %2;" : "=r"(r) : "f"(hi), "f"(lo));
    return r;
}

// ------------------------------ GEMM (fp16 mma) ------------------------------
// C[M,N] = A[M,K]@B[N,K]^T, fp16. CTA 128x128, BK=32, 256 thr (8 warps 2x4,
// warp 64x32). 3-stage cp.async pipeline; ldmatrix fragments.
#define GROW 80
#define STAGE_B 20480
#define GSMEM (3 * STAGE_B)

__global__ void __launch_bounds__(256, 2) gemm_h_kernel(
    const __half* __restrict__ A, const __half* __restrict__ B,
    __half* __restrict__ C, int M, int N, int K)
{
    extern __shared__ char smem[];
    const uint32_t sbase = smem_u32(smem);

    const int tid = threadIdx.x, lane = tid & 31, wid = tid >> 5;
    const int wm = wid & 1, wn = wid >> 1;
    const int bm = blockIdx.y * 128, bn = blockIdx.x * 128;
    const int KSTEPS = K >> 5;

    const int c_row = tid >> 2;
    const int c_ch  = tid & 3;
    auto ld_stage = [&](int ks, int buf) {
        const uint32_t sa = sbase + buf * STAGE_B;
        const int k0 = ks * 32;
#pragma unroll
        for (int h = 0; h < 2; h++) {
            cp16(sa + (c_row + h * 64) * GROW + c_ch * 16,
                 A + (size_t)(bm + c_row + h * 64) * K + k0 + c_ch * 8);
            cp16(sa + 10240 + (c_row + h * 64) * GROW + c_ch * 16,
                 B + (size_t)(bn + c_row + h * 64) * K + k0 + c_ch * 8);
        }
        cp_commit();
    };

    float acc[4][4][4];
#pragma unroll
    for (int mt = 0; mt < 4; mt++)
#pragma unroll
        for (int nt = 0; nt < 4; nt++)
#pragma unroll
            for (int i = 0; i < 4; i++) acc[mt][nt][i] = 0.f;

    const int l7 = lane & 7;
    const uint32_t aOff = (uint32_t)((wm * 64 + l7 + ((lane >> 3) & 1) * 8) * GROW
                                     + (lane >> 4) * 16);
    const uint32_t bOff = (uint32_t)(10240 + (wn * 32 + (lane >> 4) * 8 + l7) * GROW
                                     + ((lane >> 3) & 1) * 16);

    ld_stage(0, 0);
    ld_stage(1, 1);

    for (int ks = 0; ks < KSTEPS; ks++) {
        if (ks == KSTEPS - 1) cp_wait<0>(); else cp_wait<1>();
        __syncthreads();
        const uint32_t sa = sbase + (ks % 3) * STAGE_B;

#pragma unroll
        for (int kt = 0; kt < 2; kt++) {
            uint32_t af[4][4], bf[4][2];
#pragma unroll
            for (int mt = 0; mt < 4; mt++)
                ldsm4(af[mt][0], af[mt][1], af[mt][2], af[mt][3],
                      sa + aOff + mt * 16 * GROW + kt * 32);
#pragma unroll
            for (int p = 0; p < 2; p++)
                ldsm4(bf[2 * p][0], bf[2 * p][1], bf[2 * p + 1][0], bf[2 * p + 1][1],
                      sa + bOff + p * 16 * GROW + kt * 32);
#pragma unroll
            for (int mt = 0; mt < 4; mt++)
#pragma unroll
                for (int nt = 0; nt < 4; nt++)
                    mma16816(acc[mt][nt], af[mt][0], af[mt][1], af[mt][2], af[mt][3],
                             bf[nt][0], bf[nt][1]);
        }
        if (ks + 2 < KSTEPS) ld_stage(ks + 2, (ks + 2) % 3);
    }

    const int r = lane >> 2, c = lane & 3;
#pragma unroll
    for (int mt = 0; mt < 4; mt++) {
        const int row = bm + wm * 64 + mt * 16 + r;
#pragma unroll
        for (int nt = 0; nt < 4; nt++) {
            const int col = bn + wn * 32 + nt * 8 + 2 * c;
            *(uint32_t*)&C[(size_t)row * N + col] =
                f22h2(acc[mt][nt][0], acc[mt][nt][1]);
            *(uint32_t*)&C[(size_t)(row + 8) * N + col] =
                f22h2(acc[mt][nt][2], acc[mt][nt][3]);
        }
    }
}

// ----------------- fused attention + output projection ----------------------
// Block = 1 window, 512 threads (16 warps). Phase B: warp = (head, row-half)
// computes 32x64 attention; o -> smem fp16. Phase C: o @ w_out^T -> out fp32.
#define QROW 776                     // halfs per qkv smem row
#define OROW 264                     // halfs per o smem row
#define BROW 24                      // halfs per w_out stage row
#define SM_O   99328                 // byte offsets in dynamic smem
#define SM_B   133120
#define BSTG   12288                 // one w_out stage: 256*24*2
#define FSMEM  157696

__global__ void __launch_bounds__(512, 1) fused_attn_proj(
    const __half* __restrict__ qkv, const float* __restrict__ biasP,
    const __half* __restrict__ wo, float* __restrict__ out)
{
    extern __shared__ char smem[];
    const uint32_t sq = smem_u32(smem);          // qkv tile: 64 x QROW halfs
    const uint32_t so = sq + SM_O;               // o tile:   64 x OROW halfs
    const uint32_t sb = sq + SM_B;               // w_out stages: 2 x 256 x BROW

    const int tid  = threadIdx.x;
    const int lane = tid & 31;
    const int wid  = tid >> 5;
    const int l7   = lane & 7;
    const int win  = blockIdx.x;

    // ---- Phase A: load window qkv ----
    // zero pad rows 49..63 (full QROW width)
    for (int idx = tid; idx < 15 * 97; idx += 512) {
        int row = 49 + idx / 97, ch = idx % 97;
        *(uint4*)(smem + (row * QROW + ch * 8) * 2) = make_uint4(0, 0, 0, 0);
    }
    const __half* gq = qkv + (size_t)win * NTOK * QKV_E;
    for (int idx = tid; idx < NTOK * 96; idx += 512) {
        int row = idx / 96, ch = idx % 96;
        cp16(sq + (row * QROW + ch * 8) * 2, gq + (size_t)row * QKV_E + ch * 8);
    }
    cp_commit();
    cp_wait<0>();
    __syncthreads();

    // ---- Phase B: attention. warp = (head h, row-half mh) ----
    {
        const int h  = wid >> 1;
        const int mh = wid & 1;
        const int qc = h * DH, kc = 256 + h * DH, vc = 512 + h * DH;

        const uint32_t qA = sq + ((mh * 32 + l7 + ((lane >> 3) & 1) * 8) * QROW
                                  + qc + (lane >> 4) * 8) * 2;
        const uint32_t kB = sq + (((lane >> 4) * 8 + l7) * QROW
                                  + kc + ((lane >> 3) & 1) * 8) * 2;
        const uint32_t vB = sq + ((l7 + ((lane >> 3) & 1) * 8) * QROW
                                  + vc + (lane >> 4) * 8) * 2;

        float s[2][8][4];
#pragma unroll
        for (int mt = 0; mt < 2; mt++)
#pragma unroll
            for (int nt = 0; nt < 8; nt++)
#pragma unroll
                for (int i = 0; i < 4; i++) s[mt][nt][i] = 0.f;

#pragma unroll
        for (int kt = 0; kt < 2; kt++) {
            uint32_t a[2][4];
#pragma unroll
            for (int mt = 0; mt < 2; mt++)
                ldsm4(a[mt][0], a[mt][1], a[mt][2], a[mt][3],
                      qA + mt * 16 * QROW * 2 + kt * 32);
#pragma unroll
            for (int p = 0; p < 4; p++) {
                uint32_t b0, b1, b2, b3;
                ldsm4(b0, b1, b2, b3, kB + p * 16 * QROW * 2 + kt * 32);
#pragma unroll
                for (int mt = 0; mt < 2; mt++) {
                    mma16816(s[mt][2 * p],     a[mt][0], a[mt][1], a[mt][2], a[mt][3], b0, b1);
                    mma16816(s[mt][2 * p + 1], a[mt][0], a[mt][1], a[mt][2], a[mt][3], b2, b3);
                }
            }
        }

        // scale + bias + softmax
        const int r = lane >> 2, c = lane & 3;
        const float* bp = biasP + h * 4096;
        float inv0[2], inv1[2];
#pragma unroll
        for (int mt = 0; mt < 2; mt++) {
            const int R0 = mh * 32 + mt * 16 + r;
#pragma unroll
            for (int nt = 0; nt < 8; nt++) {
                float2 b0 = *(const float2*)&bp[R0 * 64 + nt * 8 + 2 * c];
                float2 b1 = *(const float2*)&bp[(R0 + 8) * 64 + nt * 8 + 2 * c];
                s[mt][nt][0] = fmaf(s[mt][nt][0], SCALE, b0.x);
                s[mt][nt][1] = fmaf(s[mt][nt][1], SCALE, b0.y);
                s[mt][nt][2] = fmaf(s[mt][nt][2], SCALE, b1.x);
                s[mt][nt][3] = fmaf(s[mt][nt][3], SCALE, b1.y);
            }
            float m0 = -1e30f, m1 = -1e30f;
#pragma unroll
            for (int nt = 0; nt < 8; nt++) {
                m0 = fmaxf(m0, fmaxf(s[mt][nt][0], s[mt][nt][1]));
                m1 = fmaxf(m1, fmaxf(s[mt][nt][2], s[mt][nt][3]));
            }
            m0 = fmaxf(m0, __shfl_xor_sync(0xffffffffu, m0, 1));
            m0 = fmaxf(m0, __shfl_xor_sync(0xffffffffu, m0, 2));
            m1 = fmaxf(m1, __shfl_xor_sync(0xffffffffu, m1, 1));
            m1 = fmaxf(m1, __shfl_xor_sync(0xffffffffu, m1, 2));
            float sum0 = 0.f, sum1 = 0.f;
#pragma unroll
            for (int nt = 0; nt < 8; nt++) {
                s[mt][nt][0] = __expf(s[mt][nt][0] - m0);
                s[mt][nt][1] = __expf(s[mt][nt][1] - m0);
                s[mt][nt][2] = __expf(s[mt][nt][2] - m1);
                s[mt][nt][3] = __expf(s[mt][nt][3] - m1);
                sum0 += s[mt][nt][0] + s[mt][nt][1];
                sum1 += s[mt][nt][2] + s[mt][nt][3];
            }
            sum0 += __shfl_xor_sync(0xffffffffu, sum0, 1);
            sum0 += __shfl_xor_sync(0xffffffffu, sum0, 2);
            sum1 += __shfl_xor_sync(0xffffffffu, sum1, 1);
            sum1 += __shfl_xor_sync(0xffffffffu, sum1, 2);
            inv0[mt] = 1.f / sum0;
            inv1[mt] = 1.f / sum1;
        }

        // P fragments (unnormalized)
        uint32_t pf[2][4][4];
#pragma unroll
        for (int mt = 0; mt < 2; mt++)
#pragma unroll
            for (int kt = 0; kt < 4; kt++) {
                pf[mt][kt][0] = f22h2(s[mt][2 * kt][0],     s[mt][2 * kt][1]);
                pf[mt][kt][1] = f22h2(s[mt][2 * kt][2],     s[mt][2 * kt][3]);
                pf[mt][kt][2] = f22h2(s[mt][2 * kt + 1][0], s[mt][2 * kt + 1][1]);
                pf[mt][kt][3] = f22h2(s[mt][2 * kt + 1][2], s[mt][2 * kt + 1][3]);
            }

        // o = P @ V
        float o[2][4][4];
#pragma unroll
        for (int mt = 0; mt < 2; mt++)
#pragma unroll
            for (int nb = 0; nb < 4; nb++)
#pragma unroll
                for (int i = 0; i < 4; i++) o[mt][nb][i] = 0.f;
#pragma unroll
        for (int kt = 0; kt < 4; kt++) {
#pragma unroll
            for (int p = 0; p < 2; p++) {
                uint32_t b0, b1, b2, b3;
                ldsm4t(b0, b1, b2, b3, vB + kt * 16 * QROW * 2 + p * 32);
#pragma unroll
                for (int mt = 0; mt < 2; mt++) {
                    mma16816(o[mt][2 * p],     pf[mt][kt][0], pf[mt][kt][1],
                             pf[mt][kt][2], pf[mt][kt][3], b0, b1);
                    mma16816(o[mt][2 * p + 1], pf[mt][kt][0], pf[mt][kt][1],
                             pf[mt][kt][2], pf[mt][kt][3], b2, b3);
                }
            }
        }

        // store o (fp16, normalized) into smem
#pragma unroll
        for (int mt = 0; mt < 2; mt++) {
            const int R0 = mh * 32 + mt * 16 + r;
#pragma unroll
            for (int nb = 0; nb < 4; nb++) {
                const int col = h * DH + nb * 8 + 2 * c;
                *(uint32_t*)(smem + SM_O + (R0 * OROW + col) * 2) =
                    f22h2(o[mt][nb][0] * inv0[mt], o[mt][nb][1] * inv0[mt]);
                *(uint32_t*)(smem + SM_O + ((R0 + 8) * OROW + col) * 2) =
                    f22h2(o[mt][nb][2] * inv1[mt], o[mt][nb][3] * inv1[mt]);
            }
        }
    }
    __syncthreads();

    // ---- Phase C: out = o @ w_out^T ----
    {
        const int wm = wid >> 2, wn = wid & 3;
        const int r = lane >> 2, c = lane & 3;
        const int bn_row = tid >> 1, bn_ch = tid & 1;   // w_out stage loader

        const uint32_t aP = so + ((wm * 16 + l7 + ((lane >> 3) & 1) * 8) * OROW
                                  + (lane >> 4) * 8) * 2;
        const uint32_t bP = sb + ((wn * 64 + (lane >> 4) * 8 + l7) * BROW
                                  + ((lane >> 3) & 1) * 8) * 2;

        float po[8][4];
#pragma unroll
        for (int nt = 0; nt < 8; nt++)
#pragma unroll
            for (int i = 0; i < 4; i++) po[nt][i] = 0.f;

        // prefetch k-step 0
        cp16(sb + (bn_row * BROW + bn_ch * 8) * 2, wo + bn_row * 256 + bn_ch * 8);
        cp_commit();

#pragma unroll
        for (int kb = 0; kb < 16; kb++) {
            cp_wait<0>();
            __syncthreads();
            if (kb < 15) {
                cp16(sb + ((kb + 1) & 1) * BSTG + (bn_row * BROW + bn_ch * 8) * 2,
                     wo + bn_row * 256 + (kb + 1) * 16 + bn_ch * 8);
                cp_commit();
            }
            uint32_t a0, a1, a2, a3;
            ldsm4(a0, a1, a2, a3, aP + kb * 32);
            const uint32_t bbuf = bP + (kb & 1) * BSTG;
#pragma unroll
            for (int p = 0; p < 4; p++) {
                uint32_t b0, b1, b2, b3;
                ldsm4(b0, b1, b2, b3, bbuf + p * 16 * BROW * 2);
                mma16816(po[2 * p],     a0, a1, a2, a3, b0, b1);
                mma16816(po[2 * p + 1], a0, a1, a2, a3, b2, b3);
            }
        }

        const int row0 = wm * 16 + r;
        float* ob = out + (size_t)win * NTOK * DIM;
#pragma unroll
        for (int nt = 0; nt < 8; nt++) {
            const int col = wn * 64 + nt * 8 + 2 * c;
            if (row0 < NTOK)
                *(float2*)&ob[(size_t)row0 * DIM + col] =
                    make_float2(po[nt][0], po[nt][1]);
            if (row0 + 8 < NTOK)
                *(float2*)&ob[(size_t)(row0 + 8) * DIM + col] =
                    make_float2(po[nt][2], po[nt][3]);
        }
    }
}

// ------------------------------ prep kernels --------------------------------
__global__ void cvt_h_kernel(const float4* __restrict__ in,
                             uint2* __restrict__ out, int n4)
{
    int i = blockIdx.x * 256 + threadIdx.x;
    if (i < n4) {
        float4 vx = in[i];
        out[i] = make_uint2(f22h2(vx.x, vx.y), f22h2(vx.z, vx.w));
    }
}

__global__ void bias_pad_kernel(const float* __restrict__ rel_emb,
                                const int* __restrict__ rel_idx,
                                float* __restrict__ biasP)
{
    int e = blockIdx.x * 256 + threadIdx.x;
    if (e < HEADS * 64 * 64) {
        int h = e >> 12, rc = e & 4095, rr = rc >> 6, cc = rc & 63;
        biasP[e] = (rr < NTOK && cc < NTOK)
                 ? rel_emb[rel_idx[rr * NTOK + cc] * HEADS + h] : -1e9f;
    }
}

// ----------------------------------------------------------------------------
extern "C" void kernel_launch(void* const* d_in, const int* in_sizes, int n_in,
                              void* d_out, int out_size)
{
    const float* x       = (const float*)d_in[0];
    const float* w_qkv   = (const float*)d_in[1];
    const float* w_out   = (const float*)d_in[2];
    const float* rel_emb = (const float*)d_in[3];
    const int*   rel_idx = (const int*)d_in[4];
    float* out = (float*)d_out;

    __half *x16, *wq16, *wo16, *qkv;
    float* biasP;
    cudaGetSymbolAddress((void**)&x16,  g_x16);
    cudaGetSymbolAddress((void**)&wq16, g_wq16);
    cudaGetSymbolAddress((void**)&wo16, g_wo16);
    cudaGetSymbolAddress((void**)&qkv,  g_qkv);
    cudaGetSymbolAddress((void**)&biasP, g_biasP);

    cudaFuncSetAttribute(gemm_h_kernel,
                         cudaFuncAttributeMaxDynamicSharedMemorySize, GSMEM);
    cudaFuncSetAttribute(fused_attn_proj,
                         cudaFuncAttributeMaxDynamicSharedMemorySize, FSMEM);

    int n4x = TTOT * DIM / 4;
    cvt_h_kernel<<<(n4x + 255) / 256, 256>>>((const float4*)x, (uint2*)x16, n4x);
    cvt_h_kernel<<<(QKV_E * DIM / 4 + 255) / 256, 256>>>(
        (const float4*)w_qkv, (uint2*)wq16, QKV_E * DIM / 4);
    cvt_h_kernel<<<(DIM * DIM / 4 + 255) / 256, 256>>>(
        (const float4*)w_out, (uint2*)wo16, DIM * DIM / 4);
    bias_pad_kernel<<<(HEADS * 64 * 64 + 255) / 256, 256>>>(rel_emb, rel_idx, biasP);

    // 1) qkv = x @ w_qkv^T
    gemm_h_kernel<<<dim3(QKV_E / 128, TTOT / 128), 256, GSMEM>>>(
        x16, wq16, qkv, TTOT, QKV_E, DIM);

    // 2) fused windowed attention + output projection
    fused_attn_proj<<<WINS, 512, FSMEM>>>(qkv, biasP, wo16, out);
}

// round 8
// speedup vs baseline: 1.1612x; 1.1612x over previous
#include <cuda_runtime.h>
#include <cuda_fp16.h>
#include <cstdint>

#define WINS   4096
#define NTOK   49
#define DIM    256
#define HEADS  8
#define DH     32
#define TTOT   (WINS * NTOK)      // 200704
#define QKV_E  768
#define SCALE  0.17677669529663687f

// ------------------------- scratch (device globals) -------------------------
__device__ __half g_x16 [(size_t)TTOT * DIM];     // 103 MB
__device__ __half g_wq16[QKV_E * DIM];
__device__ __half g_wo16[DIM * DIM];
__device__ __half g_qkv [(size_t)TTOT * QKV_E];   // 308 MB
__device__ __half g_att [(size_t)TTOT * DIM];     // 103 MB
__device__ float  g_biasP[HEADS * 64 * 64];       // padded bias

// ------------------------------ helpers ------------------------------------
__device__ __forceinline__ uint32_t smem_u32(const void* p) {
    uint32_t a;
    asm("{ .reg .u64 t; cvta.to.shared.u64 t, %1; cvt.u32.u64 %0, t; }"
        : "=r"(a) : "l"(p));
    return a;
}
__device__ __forceinline__ void cp16(uint32_t dst, const void* src) {
    asm volatile("cp.async.cg.shared.global [%0], [%1], 16;\n" :: "r"(dst), "l"(src));
}
__device__ __forceinline__ void cp16ca(uint32_t dst, const void* src) {
    asm volatile("cp.async.ca.shared.global [%0], [%1], 16;\n" :: "r"(dst), "l"(src));
}
__device__ __forceinline__ void cp_commit() {
    asm volatile("cp.async.commit_group;\n" ::);
}
template <int N> __device__ __forceinline__ void cp_wait() {
    asm volatile("cp.async.wait_group %0;\n" :: "n"(N) : "memory");
}
__device__ __forceinline__ void ldsm4(uint32_t& r0, uint32_t& r1, uint32_t& r2,
                                      uint32_t& r3, uint32_t a) {
    asm volatile("ldmatrix.sync.aligned.m8n8.x4.shared.b16 {%0,%1,%2,%3}, [%4];"
                 : "=r"(r0), "=r"(r1), "=r"(r2), "=r"(r3) : "r"(a) : "memory");
}
__device__ __forceinline__ void ldsm4t(uint32_t& r0, uint32_t& r1, uint32_t& r2,
                                       uint32_t& r3, uint32_t a) {
    asm volatile("ldmatrix.sync.aligned.m8n8.x4.trans.shared.b16 {%0,%1,%2,%3}, [%4];"
                 : "=r"(r0), "=r"(r1), "=r"(r2), "=r"(r3) : "r"(a) : "memory");
}
__device__ __forceinline__ void mma16816(float* d, uint32_t a0, uint32_t a1,
                                         uint32_t a2, uint32_t a3,
                                         uint32_t b0, uint32_t b1) {
    asm volatile(
        "mma.sync.aligned.m16n8k16.row.col.f32.f16.f16.f32 "
        "{%0,%1,%2,%3}, {%4,%5,%6,%7}, {%8,%9}, {%0,%1,%2,%3};"
        : "+f"(d[0]), "+f"(d[1]), "+f"(d[2]), "+f"(d[3])
        : "r"(a0), "r"(a1), "r"(a2), "r"(a3), "r"(b0), "r"(b1));
}
__device__ __forceinline__ uint32_t f22h2(float lo, float hi) {
    uint32_t r;
    asm("cvt.rn.f16x2.f32 %0, %1, %2;" : "=r"(r) : "f"(hi), "f"(lo));
    return r;
}

// ------------------------------ GEMM (fp16 mma) ------------------------------
// C[M,N] = A[M,K]@B[N,K]^T, fp16. CTA 128x128, BK=32, 256 thr (8 warps 2x4,
// warp 64x32). 4-stage cp.async pipeline; ldmatrix fragments.
#define GROW 80
#define STAGE_B 20480
#define NST 4
#define GSMEM (NST * STAGE_B)        // 81920

template <int HALF_OUT>
__global__ void __launch_bounds__(256, 2) gemm_h_kernel(
    const __half* __restrict__ A, const __half* __restrict__ B,
    void* __restrict__ Cv, int M, int N, int K)
{
    extern __shared__ char smem[];
    const uint32_t sbase = smem_u32(smem);

    const int tid = threadIdx.x, lane = tid & 31, wid = tid >> 5;
    const int wm = wid & 1, wn = wid >> 1;
    const int bm = blockIdx.y * 128, bn = blockIdx.x * 128;
    const int KSTEPS = K >> 5;

    const int c_row = tid >> 2;
    const int c_ch  = tid & 3;
    auto ld_stage = [&](int ks, int buf) {
        const uint32_t sa = sbase + buf * STAGE_B;
        const int k0 = ks * 32;
#pragma unroll
        for (int h = 0; h < 2; h++) {
            cp16(sa + (c_row + h * 64) * GROW + c_ch * 16,
                 A + (size_t)(bm + c_row + h * 64) * K + k0 + c_ch * 8);
            cp16(sa + 10240 + (c_row + h * 64) * GROW + c_ch * 16,
                 B + (size_t)(bn + c_row + h * 64) * K + k0 + c_ch * 8);
        }
        cp_commit();
    };

    float acc[4][4][4];
#pragma unroll
    for (int mt = 0; mt < 4; mt++)
#pragma unroll
        for (int nt = 0; nt < 4; nt++)
#pragma unroll
            for (int i = 0; i < 4; i++) acc[mt][nt][i] = 0.f;

    const int l7 = lane & 7;
    const uint32_t aOff = (uint32_t)((wm * 64 + l7 + ((lane >> 3) & 1) * 8) * GROW
                                     + (lane >> 4) * 16);
    const uint32_t bOff = (uint32_t)(10240 + (wn * 32 + (lane >> 4) * 8 + l7) * GROW
                                     + ((lane >> 3) & 1) * 16);

    ld_stage(0, 0);
    if (KSTEPS > 1) ld_stage(1, 1);
    if (KSTEPS > 2) ld_stage(2, 2);

    for (int ks = 0; ks < KSTEPS; ks++) {
        const int rem = KSTEPS - 1 - ks;
        if (rem >= 2) cp_wait<2>(); else if (rem == 1) cp_wait<1>(); else cp_wait<0>();
        __syncthreads();
        const uint32_t sa = sbase + (ks % NST) * STAGE_B;

#pragma unroll
        for (int kt = 0; kt < 2; kt++) {
            uint32_t af[4][4], bf[4][2];
#pragma unroll
            for (int mt = 0; mt < 4; mt++)
                ldsm4(af[mt][0], af[mt][1], af[mt][2], af[mt][3],
                      sa + aOff + mt * 16 * GROW + kt * 32);
#pragma unroll
            for (int p = 0; p < 2; p++)
                ldsm4(bf[2 * p][0], bf[2 * p][1], bf[2 * p + 1][0], bf[2 * p + 1][1],
                      sa + bOff + p * 16 * GROW + kt * 32);
#pragma unroll
            for (int mt = 0; mt < 4; mt++)
#pragma unroll
                for (int nt = 0; nt < 4; nt++)
                    mma16816(acc[mt][nt], af[mt][0], af[mt][1], af[mt][2], af[mt][3],
                             bf[nt][0], bf[nt][1]);
        }
        if (ks + 3 < KSTEPS) ld_stage(ks + 3, (ks + 3) % NST);
    }

    const int r = lane >> 2, c = lane & 3;
#pragma unroll
    for (int mt = 0; mt < 4; mt++) {
        const int row = bm + wm * 64 + mt * 16 + r;
#pragma unroll
        for (int nt = 0; nt < 4; nt++) {
            const int col = bn + wn * 32 + nt * 8 + 2 * c;
            if (HALF_OUT) {
                __half* C = (__half*)Cv;
                *(uint32_t*)&C[(size_t)row * N + col] =
                    f22h2(acc[mt][nt][0], acc[mt][nt][1]);
                *(uint32_t*)&C[(size_t)(row + 8) * N + col] =
                    f22h2(acc[mt][nt][2], acc[mt][nt][3]);
            } else {
                float* C = (float*)Cv;
                *(float2*)&C[(size_t)row * N + col] =
                    make_float2(acc[mt][nt][0], acc[mt][nt][1]);
                *(float2*)&C[(size_t)(row + 8) * N + col] =
                    make_float2(acc[mt][nt][2], acc[mt][nt][3]);
            }
        }
    }
}

// --------------------------- attention (fp16 mma) ---------------------------
// Block = 2 x (window, head), 256 threads (4 warps per pair). Padded 64x64
// tiles; bias(-1e9) masks pads. P stays in registers (A-fragment layout).
#define AROW 40                         // halfs per smem row (80B)

__global__ void __launch_bounds__(256, 2) attn_kernel(
    const __half* __restrict__ qkv, const float* __restrict__ biasP,
    __half* __restrict__ att)
{
    __shared__ __half sq[2][64 * AROW];
    __shared__ __half sk[2][64 * AROW];
    __shared__ __half sv[2][64 * AROW];

    const int tid = threadIdx.x;
    const int sub = tid >> 7;
    const int st  = tid & 127;
    const int lane = tid & 31;
    const int w   = (tid >> 5) & 3;
    const int pair = blockIdx.x * 2 + sub;
    const int win = pair >> 3, head = pair & 7;

    __half* q = sq[sub]; __half* k = sk[sub]; __half* v = sv[sub];

    for (int idx = st; idx < 180; idx += 128) {
        int m = idx / 60, rc = idx % 60;
        int row = 49 + rc / 4, ch = rc & 3;
        __half* base = (m == 0 ? q : (m == 1 ? k : v));
        *(uint4*)&base[row * AROW + ch * 8] = make_uint4(0, 0, 0, 0);
    }
    const __half* gbase = qkv + (size_t)win * NTOK * QKV_E + head * DH;
    for (int idx = st; idx < 588; idx += 128) {
        int m = idx / 196, rc = idx % 196;
        int row = rc >> 2, ch = rc & 3;
        __half* base = (m == 0 ? q : (m == 1 ? k : v));
        cp16ca(smem_u32(&base[row * AROW + ch * 8]),
               gbase + (size_t)row * QKV_E + m * DIM + ch * 8);
    }
    cp_commit();
    cp_wait<0>();
    __syncthreads();

    const int l7 = lane & 7;
    const int wr = w * 16;
    const uint32_t qA = smem_u32(&q[(wr + l7 + ((lane >> 3) & 1) * 8) * AROW
                                    + (lane >> 4) * 8]);
    const uint32_t kB = smem_u32(&k[((lane >> 4) * 8 + l7) * AROW
                                    + ((lane >> 3) & 1) * 8]);
    const uint32_t vB = smem_u32(&v[(l7 + ((lane >> 3) & 1) * 8) * AROW
                                    + (lane >> 4) * 8]);

    float s[8][4];
#pragma unroll
    for (int nt = 0; nt < 8; nt++)
#pragma unroll
        for (int i = 0; i < 4; i++) s[nt][i] = 0.f;

#pragma unroll
    for (int kt = 0; kt < 2; kt++) {
        uint32_t a0, a1, a2, a3;
        ldsm4(a0, a1, a2, a3, qA + kt * 16 * 2);
#pragma unroll
        for (int p = 0; p < 4; p++) {
            uint32_t b0, b1, b2, b3;
            ldsm4(b0, b1, b2, b3, kB + p * 16 * AROW * 2 + kt * 32);
            mma16816(s[2 * p],     a0, a1, a2, a3, b0, b1);
            mma16816(s[2 * p + 1], a0, a1, a2, a3, b2, b3);
        }
    }

    const int r = lane >> 2, c = lane & 3;
    const float* bp = biasP + head * 4096;
#pragma unroll
    for (int nt = 0; nt < 8; nt++) {
        float2 b0 = *(const float2*)&bp[(wr + r) * 64 + nt * 8 + 2 * c];
        float2 b1 = *(const float2*)&bp[(wr + r + 8) * 64 + nt * 8 + 2 * c];
        s[nt][0] = fmaf(s[nt][0], SCALE, b0.x);
        s[nt][1] = fmaf(s[nt][1], SCALE, b0.y);
        s[nt][2] = fmaf(s[nt][2], SCALE, b1.x);
        s[nt][3] = fmaf(s[nt][3], SCALE, b1.y);
    }
    float m0 = -1e30f, m1 = -1e30f;
#pragma unroll
    for (int nt = 0; nt < 8; nt++) {
        m0 = fmaxf(m0, fmaxf(s[nt][0], s[nt][1]));
        m1 = fmaxf(m1, fmaxf(s[nt][2], s[nt][3]));
    }
    m0 = fmaxf(m0, __shfl_xor_sync(0xffffffffu, m0, 1));
    m0 = fmaxf(m0, __shfl_xor_sync(0xffffffffu, m0, 2));
    m1 = fmaxf(m1, __shfl_xor_sync(0xffffffffu, m1, 1));
    m1 = fmaxf(m1, __shfl_xor_sync(0xffffffffu, m1, 2));
    float sum0 = 0.f, sum1 = 0.f;
#pragma unroll
    for (int nt = 0; nt < 8; nt++) {
        s[nt][0] = __expf(s[nt][0] - m0);
        s[nt][1] = __expf(s[nt][1] - m0);
        s[nt][2] = __expf(s[nt][2] - m1);
        s[nt][3] = __expf(s[nt][3] - m1);
        sum0 += s[nt][0] + s[nt][1];
        sum1 += s[nt][2] + s[nt][3];
    }
    sum0 += __shfl_xor_sync(0xffffffffu, sum0, 1);
    sum0 += __shfl_xor_sync(0xffffffffu, sum0, 2);
    sum1 += __shfl_xor_sync(0xffffffffu, sum1, 1);
    sum1 += __shfl_xor_sync(0xffffffffu, sum1, 2);
    const float inv0 = 1.f / sum0, inv1 = 1.f / sum1;

    uint32_t pf[4][4];
#pragma unroll
    for (int kt = 0; kt < 4; kt++) {
        pf[kt][0] = f22h2(s[2 * kt][0],     s[2 * kt][1]);
        pf[kt][1] = f22h2(s[2 * kt][2],     s[2 * kt][3]);
        pf[kt][2] = f22h2(s[2 * kt + 1][0], s[2 * kt + 1][1]);
        pf[kt][3] = f22h2(s[2 * kt + 1][2], s[2 * kt + 1][3]);
    }

    float o[4][4];
#pragma unroll
    for (int nb = 0; nb < 4; nb++)
#pragma unroll
        for (int i = 0; i < 4; i++) o[nb][i] = 0.f;
#pragma unroll
    for (int kt = 0; kt < 4; kt++) {
#pragma unroll
        for (int p = 0; p < 2; p++) {
            uint32_t b0, b1, b2, b3;
            ldsm4t(b0, b1, b2, b3, vB + kt * 16 * AROW * 2 + p * 32);
            mma16816(o[2 * p],     pf[kt][0], pf[kt][1], pf[kt][2], pf[kt][3], b0, b1);
            mma16816(o[2 * p + 1], pf[kt][0], pf[kt][1], pf[kt][2], pf[kt][3], b2, b3);
        }
    }

    const int row0 = wr + r, row1 = wr + r + 8;
#pragma unroll
    for (int nb = 0; nb < 4; nb++) {
        const int col = head * DH + nb * 8 + 2 * c;
        if (row0 < NTOK)
            *(uint32_t*)&att[((size_t)win * NTOK + row0) * DIM + col] =
                f22h2(o[nb][0] * inv0, o[nb][1] * inv0);
        if (row1 < NTOK)
            *(uint32_t*)&att[((size_t)win * NTOK + row1) * DIM + col] =
                f22h2(o[nb][2] * inv1, o[nb][3] * inv1);
    }
}

// ------------------------------ prep kernels --------------------------------
__global__ void cvt_h_kernel(const float4* __restrict__ in,
                             uint2* __restrict__ out, int n4)
{
    int i = blockIdx.x * 256 + threadIdx.x;
    if (i < n4) {
        float4 vx = in[i];
        out[i] = make_uint2(f22h2(vx.x, vx.y), f22h2(vx.z, vx.w));
    }
}

// weights cvt + bias pad, one launch
__global__ void prep_small_kernel(const float4* __restrict__ wq,
                                  const float4* __restrict__ wo,
                                  const float*  __restrict__ rel_emb,
                                  const int*    __restrict__ rel_idx,
                                  uint2* __restrict__ wq16,
                                  uint2* __restrict__ wo16,
                                  float* __restrict__ biasP)
{
    const int NWQ = QKV_E * DIM / 4;          // 49152
    const int NWO = DIM * DIM / 4;            // 16384
    const int NB  = HEADS * 64 * 64;          // 32768
    int i = blockIdx.x * 256 + threadIdx.x;
    if (i < NWQ) {
        float4 v = wq[i];
        wq16[i] = make_uint2(f22h2(v.x, v.y), f22h2(v.z, v.w));
    } else if (i < NWQ + NWO) {
        int j = i - NWQ;
        float4 v = wo[j];
        wo16[j] = make_uint2(f22h2(v.x, v.y), f22h2(v.z, v.w));
    } else if (i < NWQ + NWO + NB) {
        int e = i - NWQ - NWO;
        int h = e >> 12, rc = e & 4095, rr = rc >> 6, cc = rc & 63;
        biasP[e] = (rr < NTOK && cc < NTOK)
                 ? rel_emb[rel_idx[rr * NTOK + cc] * HEADS + h] : -1e9f;
    }
}

// ----------------------------------------------------------------------------
extern "C" void kernel_launch(void* const* d_in, const int* in_sizes, int n_in,
                              void* d_out, int out_size)
{
    const float* x       = (const float*)d_in[0];
    const float* w_qkv   = (const float*)d_in[1];
    const float* w_out   = (const float*)d_in[2];
    const float* rel_emb = (const float*)d_in[3];
    const int*   rel_idx = (const int*)d_in[4];
    float* out = (float*)d_out;

    __half *x16, *wq16, *wo16, *qkv, *att;
    float* biasP;
    cudaGetSymbolAddress((void**)&x16,  g_x16);
    cudaGetSymbolAddress((void**)&wq16, g_wq16);
    cudaGetSymbolAddress((void**)&wo16, g_wo16);
    cudaGetSymbolAddress((void**)&qkv,  g_qkv);
    cudaGetSymbolAddress((void**)&att,  g_att);
    cudaGetSymbolAddress((void**)&biasP, g_biasP);

    cudaFuncSetAttribute(gemm_h_kernel<1>,
                         cudaFuncAttributeMaxDynamicSharedMemorySize, GSMEM);
    cudaFuncSetAttribute(gemm_h_kernel<0>,
                         cudaFuncAttributeMaxDynamicSharedMemorySize, GSMEM);

    int n4x = TTOT * DIM / 4;
    cvt_h_kernel<<<(n4x + 255) / 256, 256>>>((const float4*)x, (uint2*)x16, n4x);
    {
        int tot = QKV_E * DIM / 4 + DIM * DIM / 4 + HEADS * 64 * 64;
        prep_small_kernel<<<(tot + 255) / 256, 256>>>(
            (const float4*)w_qkv, (const float4*)w_out, rel_emb, rel_idx,
            (uint2*)wq16, (uint2*)wo16, biasP);
    }

    // 1) qkv = x @ w_qkv^T
    gemm_h_kernel<1><<<dim3(QKV_E / 128, TTOT / 128), 256, GSMEM>>>(
        x16, wq16, qkv, TTOT, QKV_E, DIM);

    // 2) windowed attention
    attn_kernel<<<WINS * HEADS / 2, 256>>>(qkv, biasP, att);

    // 3) out = att @ w_out^T
    gemm_h_kernel<0><<<dim3(DIM / 128, TTOT / 128), 256, GSMEM>>>(
        att, wo16, out, TTOT, DIM, DIM);
}

// round 9
// speedup vs baseline: 1.2187x; 1.0495x over previous
#include <cuda_runtime.h>
#include <cuda_fp16.h>
#include <cstdint>

#define WINS   4096
#define NTOK   49
#define DIM    256
#define HEADS  8
#define DH     32
#define TTOT   (WINS * NTOK)      // 200704
#define QKV_E  768
#define SCALE  0.17677669529663687f

// ------------------------- scratch (device globals) -------------------------
__device__ __half g_x16 [(size_t)TTOT * DIM];     // 103 MB
__device__ __half g_wq16[QKV_E * DIM];
__device__ __half g_wo16[DIM * DIM];
__device__ __half g_qkv [(size_t)TTOT * QKV_E];   // 308 MB
__device__ __half g_att [(size_t)TTOT * DIM];     // 103 MB
__device__ float  g_biasP[HEADS * 64 * 64];       // padded bias

// ------------------------------ helpers ------------------------------------
__device__ __forceinline__ uint32_t smem_u32(const void* p) {
    uint32_t a;
    asm("{ .reg .u64 t; cvta.to.shared.u64 t, %1; cvt.u32.u64 %0, t; }"
        : "=r"(a) : "l"(p));
    return a;
}
__device__ __forceinline__ void cp16(uint32_t dst, const void* src) {
    asm volatile("cp.async.cg.shared.global [%0], [%1], 16;\n" :: "r"(dst), "l"(src));
}
__device__ __forceinline__ void cp_commit() {
    asm volatile("cp.async.commit_group;\n" ::);
}
template <int N> __device__ __forceinline__ void cp_wait() {
    asm volatile("cp.async.wait_group %0;\n" :: "n"(N) : "memory");
}
__device__ __forceinline__ void ldsm4(uint32_t& r0, uint32_t& r1, uint32_t& r2,
                                      uint32_t& r3, uint32_t a) {
    asm volatile("ldmatrix.sync.aligned.m8n8.x4.shared.b16 {%0,%1,%2,%3}, [%4];"
                 : "=r"(r0), "=r"(r1), "=r"(r2), "=r"(r3) : "r"(a) : "memory");
}
__device__ __forceinline__ void ldsm4t(uint32_t& r0, uint32_t& r1, uint32_t& r2,
                                       uint32_t& r3, uint32_t a) {
    asm volatile("ldmatrix.sync.aligned.m8n8.x4.trans.shared.b16 {%0,%1,%2,%3}, [%4];"
                 : "=r"(r0), "=r"(r1), "=r"(r2), "=r"(r3) : "r"(a) : "memory");
}
__device__ __forceinline__ void mma16816(float* d, uint32_t a0, uint32_t a1,
                                         uint32_t a2, uint32_t a3,
                                         uint32_t b0, uint32_t b1) {
    asm volatile(
        "mma.sync.aligned.m16n8k16.row.col.f32.f16.f16.f32 "
        "{%0,%1,%2,%3}, {%4,%5,%6,%7}, {%8,%9}, {%0,%1,%2,%3};"
        : "+f"(d[0]), "+f"(d[1]), "+f"(d[2]), "+f"(d[3])
        : "r"(a0), "r"(a1), "r"(a2), "r"(a3), "r"(b0), "r"(b1));
}
__device__ __forceinline__ uint32_t f22h2(float lo, float hi) {
    uint32_t r;
    asm("cvt.rn.f16x2.f32 %0, %1, %2;" : "=r"(r) : "f"(hi), "f"(lo));
    return r;
}

// ---------------------- GEMM (fp16 mma, A-resident) --------------------------
// C[M,N] = A[M,K=256]@B[N,256]^T. CTA owns 128 A-rows, loads the FULL 128x256
// A slab into smem once, then loops n-tiles (128 cols each) streaming B through
// a 3-stage cp.async pipeline (B is L2-resident). 256 thr, 8 warps (2x4).
#define SAROW 528                   // bytes per sA row (256 halfs + 16B pad)
#define SA_BYTES (128 * SAROW)      // 67584
#define BGROW 80                    // bytes per sB row
#define BST  (128 * BGROW)          // 10240 per stage
#define NSTG 3
#define GSMEM (SA_BYTES + NSTG * BST)   // 98304

template <int HALF_OUT>
__global__ void __launch_bounds__(256, 2) gemm_h_kernel(
    const __half* __restrict__ A, const __half* __restrict__ B,
    void* __restrict__ Cv, int N)
{
    extern __shared__ char smem[];
    const uint32_t sA = smem_u32(smem);
    const uint32_t sB = sA + SA_BYTES;

    const int tid = threadIdx.x, lane = tid & 31, wid = tid >> 5;
    const int wm = wid & 1, wn = wid >> 1;
    const int bm = blockIdx.x * 128;
    const int ntiles = N >> 7;
    const int NQ = ntiles * 8;           // total B-tile stream steps

    // ---- load full A slab (128 x 256 halfs), 16 chunks/thread ----
#pragma unroll
    for (int it = 0; it < 16; it++) {
        int idx = tid + it * 256;        // 4096 chunks
        int row = idx >> 5, ch = idx & 31;
        cp16(sA + row * SAROW + ch * 16,
             A + (size_t)(bm + row) * DIM + ch * 8);
    }
    cp_commit();

    // ---- B stage loader: stream index q = nt*8 + ks ----
    const int b_row = tid >> 1;
    auto ld_B = [&](int q, int buf) {
        const int nt = q >> 3, ks = q & 7;
        const __half* src = B + (size_t)(nt * 128 + b_row) * DIM + ks * 32;
#pragma unroll
        for (int h = 0; h < 2; h++) {
            int ch = (tid & 1) + h * 2;
            cp16(sB + buf * BST + b_row * BGROW + ch * 16, src + ch * 8);
        }
        cp_commit();
    };
    ld_B(0, 0);
    ld_B(1, 1);

    const int l7 = lane & 7;
    const uint32_t aBase = sA + (wm * 64 + l7 + ((lane >> 3) & 1) * 8) * SAROW
                              + (lane >> 4) * 16;
    const uint32_t bBase = sB + (wn * 32 + (lane >> 4) * 8 + l7) * BGROW
                              + ((lane >> 3) & 1) * 16;

    const int r = lane >> 2, c = lane & 3;

    for (int nt = 0; nt < ntiles; nt++) {
        float acc[4][4][4];
#pragma unroll
        for (int mt = 0; mt < 4; mt++)
#pragma unroll
            for (int ntt = 0; ntt < 4; ntt++)
#pragma unroll
                for (int i = 0; i < 4; i++) acc[mt][ntt][i] = 0.f;

#pragma unroll
        for (int ks = 0; ks < 8; ks++) {
            const int q = nt * 8 + ks;
            if (q + 1 < NQ) cp_wait<1>(); else cp_wait<0>();
            __syncthreads();
            const uint32_t sb = sB + (q % NSTG) * BST - sB + sB; // keep simple
            const uint32_t bcur = bBase + (q % NSTG) * BST - 0;

#pragma unroll
            for (int kt = 0; kt < 2; kt++) {
                uint32_t af[4][4], bf[4][2];
#pragma unroll
                for (int mt = 0; mt < 4; mt++)
                    ldsm4(af[mt][0], af[mt][1], af[mt][2], af[mt][3],
                          aBase + mt * 16 * SAROW + ks * 64 + kt * 32);
#pragma unroll
                for (int p = 0; p < 2; p++)
                    ldsm4(bf[2 * p][0], bf[2 * p][1], bf[2 * p + 1][0], bf[2 * p + 1][1],
                          bcur + p * 16 * BGROW + kt * 32);
#pragma unroll
                for (int mt = 0; mt < 4; mt++)
#pragma unroll
                    for (int ntt = 0; ntt < 4; ntt++)
                        mma16816(acc[mt][ntt], af[mt][0], af[mt][1], af[mt][2], af[mt][3],
                                 bf[ntt][0], bf[ntt][1]);
            }
            __syncthreads();             // stage consumed; safe to overwrite
            if (q + 2 < NQ) ld_B(q + 2, (q + 2) % NSTG);
        }

        // epilogue for this n-tile
        const int bn = nt * 128;
#pragma unroll
        for (int mt = 0; mt < 4; mt++) {
            const int row = bm + wm * 64 + mt * 16 + r;
#pragma unroll
            for (int ntt = 0; ntt < 4; ntt++) {
                const int col = bn + wn * 32 + ntt * 8 + 2 * c;
                if (HALF_OUT) {
                    __half* C = (__half*)Cv;
                    *(uint32_t*)&C[(size_t)row * N + col] =
                        f22h2(acc[mt][ntt][0], acc[mt][ntt][1]);
                    *(uint32_t*)&C[(size_t)(row + 8) * N + col] =
                        f22h2(acc[mt][ntt][2], acc[mt][ntt][3]);
                } else {
                    float* C = (float*)Cv;
                    *(float2*)&C[(size_t)row * N + col] =
                        make_float2(acc[mt][ntt][0], acc[mt][ntt][1]);
                    *(float2*)&C[(size_t)(row + 8) * N + col] =
                        make_float2(acc[mt][ntt][2], acc[mt][ntt][3]);
                }
            }
        }
    }
}

// --------------------------- attention (fp16 mma) ---------------------------
// Block = one (window, head), 128 threads (4 warps), division-free loaders.
#define AROW 40                         // halfs per smem row (80B)

__global__ void __launch_bounds__(128, 5) attn_kernel(
    const __half* __restrict__ qkv, const float* __restrict__ biasP,
    __half* __restrict__ att)
{
    __shared__ __half q[64 * AROW];
    __shared__ __half k[64 * AROW];
    __shared__ __half v[64 * AROW];

    const int tid  = threadIdx.x;
    const int lane = tid & 31;
    const int w    = tid >> 5;
    const int win  = blockIdx.x >> 3, head = blockIdx.x & 7;

    // zero pad rows 49..63: 60 chunks per matrix (15 rows x 4), threads 0..59
    {
        int rc = tid & 63;               // 0..63
        if (rc < 60) {
            int row = 49 + (rc >> 2), ch = rc & 3;
            __half* base = (tid < 64) ? q : k;
            *(uint4*)&base[row * AROW + ch * 8] = make_uint4(0, 0, 0, 0);
            if (tid < 64) { // thread also zeroes v (3 matrices, 2 groups of 64)
                *(uint4*)&v[row * AROW + ch * 8] = make_uint4(0, 0, 0, 0);
            }
        }
    }
    // load q,k,v rows 0..48 (196 chunks each), division-free
    const __half* gbase = qkv + (size_t)win * NTOK * QKV_E + head * DH;
#pragma unroll
    for (int m = 0; m < 3; m++) {
        __half* base = (m == 0 ? q : (m == 1 ? k : v));
        const __half* gsrc = gbase + m * DIM;
#pragma unroll
        for (int it = 0; it < 2; it++) {
            int u = tid + it * 128;      // 0..255, need < 196
            if (u < 196) {
                int row = u >> 2, ch = u & 3;
                cp16(smem_u32(&base[row * AROW + ch * 8]),
                     gsrc + (size_t)row * QKV_E + ch * 8);
            }
        }
    }
    cp_commit();
    cp_wait<0>();
    __syncthreads();

    const int l7 = lane & 7;
    const int wr = w * 16;
    const uint32_t qA = smem_u32(&q[(wr + l7 + ((lane >> 3) & 1) * 8) * AROW
                                    + (lane >> 4) * 8]);
    const uint32_t kB = smem_u32(&k[((lane >> 4) * 8 + l7) * AROW
                                    + ((lane >> 3) & 1) * 8]);
    const uint32_t vB = smem_u32(&v[(l7 + ((lane >> 3) & 1) * 8) * AROW
                                    + (lane >> 4) * 8]);

    float s[8][4];
#pragma unroll
    for (int nt = 0; nt < 8; nt++)
#pragma unroll
        for (int i = 0; i < 4; i++) s[nt][i] = 0.f;

#pragma unroll
    for (int kt = 0; kt < 2; kt++) {
        uint32_t a0, a1, a2, a3;
        ldsm4(a0, a1, a2, a3, qA + kt * 32);
#pragma unroll
        for (int p = 0; p < 4; p++) {
            uint32_t b0, b1, b2, b3;
            ldsm4(b0, b1, b2, b3, kB + p * 16 * AROW * 2 + kt * 32);
            mma16816(s[2 * p],     a0, a1, a2, a3, b0, b1);
            mma16816(s[2 * p + 1], a0, a1, a2, a3, b2, b3);
        }
    }

    const int r = lane >> 2, c = lane & 3;
    const float* bp = biasP + head * 4096;
#pragma unroll
    for (int nt = 0; nt < 8; nt++) {
        float2 b0 = *(const float2*)&bp[(wr + r) * 64 + nt * 8 + 2 * c];
        float2 b1 = *(const float2*)&bp[(wr + r + 8) * 64 + nt * 8 + 2 * c];
        s[nt][0] = fmaf(s[nt][0], SCALE, b0.x);
        s[nt][1] = fmaf(s[nt][1], SCALE, b0.y);
        s[nt][2] = fmaf(s[nt][2], SCALE, b1.x);
        s[nt][3] = fmaf(s[nt][3], SCALE, b1.y);
    }
    float m0 = -1e30f, m1 = -1e30f;
#pragma unroll
    for (int nt = 0; nt < 8; nt++) {
        m0 = fmaxf(m0, fmaxf(s[nt][0], s[nt][1]));
        m1 = fmaxf(m1, fmaxf(s[nt][2], s[nt][3]));
    }
    m0 = fmaxf(m0, __shfl_xor_sync(0xffffffffu, m0, 1));
    m0 = fmaxf(m0, __shfl_xor_sync(0xffffffffu, m0, 2));
    m1 = fmaxf(m1, __shfl_xor_sync(0xffffffffu, m1, 1));
    m1 = fmaxf(m1, __shfl_xor_sync(0xffffffffu, m1, 2));
    float sum0 = 0.f, sum1 = 0.f;
#pragma unroll
    for (int nt = 0; nt < 8; nt++) {
        s[nt][0] = __expf(s[nt][0] - m0);
        s[nt][1] = __expf(s[nt][1] - m0);
        s[nt][2] = __expf(s[nt][2] - m1);
        s[nt][3] = __expf(s[nt][3] - m1);
        sum0 += s[nt][0] + s[nt][1];
        sum1 += s[nt][2] + s[nt][3];
    }
    sum0 += __shfl_xor_sync(0xffffffffu, sum0, 1);
    sum0 += __shfl_xor_sync(0xffffffffu, sum0, 2);
    sum1 += __shfl_xor_sync(0xffffffffu, sum1, 1);
    sum1 += __shfl_xor_sync(0xffffffffu, sum1, 2);
    const float inv0 = 1.f / sum0, inv1 = 1.f / sum1;

    uint32_t pf[4][4];
#pragma unroll
    for (int kt = 0; kt < 4; kt++) {
        pf[kt][0] = f22h2(s[2 * kt][0],     s[2 * kt][1]);
        pf[kt][1] = f22h2(s[2 * kt][2],     s[2 * kt][3]);
        pf[kt][2] = f22h2(s[2 * kt + 1][0], s[2 * kt + 1][1]);
        pf[kt][3] = f22h2(s[2 * kt + 1][2], s[2 * kt + 1][3]);
    }

    float o[4][4];
#pragma unroll
    for (int nb = 0; nb < 4; nb++)
#pragma unroll
        for (int i = 0; i < 4; i++) o[nb][i] = 0.f;
#pragma unroll
    for (int kt = 0; kt < 4; kt++) {
#pragma unroll
        for (int p = 0; p < 2; p++) {
            uint32_t b0, b1, b2, b3;
            ldsm4t(b0, b1, b2, b3, vB + kt * 16 * AROW * 2 + p * 32);
            mma16816(o[2 * p],     pf[kt][0], pf[kt][1], pf[kt][2], pf[kt][3], b0, b1);
            mma16816(o[2 * p + 1], pf[kt][0], pf[kt][1], pf[kt][2], pf[kt][3], b2, b3);
        }
    }

    const int row0 = wr + r, row1 = wr + r + 8;
#pragma unroll
    for (int nb = 0; nb < 4; nb++) {
        const int col = head * DH + nb * 8 + 2 * c;
        if (row0 < NTOK)
            *(uint32_t*)&att[((size_t)win * NTOK + row0) * DIM + col] =
                f22h2(o[nb][0] * inv0, o[nb][1] * inv0);
        if (row1 < NTOK)
            *(uint32_t*)&att[((size_t)win * NTOK + row1) * DIM + col] =
                f22h2(o[nb][2] * inv1, o[nb][3] * inv1);
    }
}

// ------------------------------ prep kernels --------------------------------
__global__ void cvt_h_kernel(const float4* __restrict__ in,
                             uint2* __restrict__ out, int n4)
{
    int i = blockIdx.x * 256 + threadIdx.x;
    if (i < n4) {
        float4 vx = in[i];
        out[i] = make_uint2(f22h2(vx.x, vx.y), f22h2(vx.z, vx.w));
    }
}

__global__ void prep_small_kernel(const float4* __restrict__ wq,
                                  const float4* __restrict__ wo,
                                  const float*  __restrict__ rel_emb,
                                  const int*    __restrict__ rel_idx,
                                  uint2* __restrict__ wq16,
                                  uint2* __restrict__ wo16,
                                  float* __restrict__ biasP)
{
    const int NWQ = QKV_E * DIM / 4;
    const int NWO = DIM * DIM / 4;
    const int NB  = HEADS * 64 * 64;
    int i = blockIdx.x * 256 + threadIdx.x;
    if (i < NWQ) {
        float4 v = wq[i];
        wq16[i] = make_uint2(f22h2(v.x, v.y), f22h2(v.z, v.w));
    } else if (i < NWQ + NWO) {
        int j = i - NWQ;
        float4 v = wo[j];
        wo16[j] = make_uint2(f22h2(v.x, v.y), f22h2(v.z, v.w));
    } else if (i < NWQ + NWO + NB) {
        int e = i - NWQ - NWO;
        int h = e >> 12, rc = e & 4095, rr = rc >> 6, cc = rc & 63;
        biasP[e] = (rr < NTOK && cc < NTOK)
                 ? rel_emb[rel_idx[rr * NTOK + cc] * HEADS + h] : -1e9f;
    }
}

// ----------------------------------------------------------------------------
extern "C" void kernel_launch(void* const* d_in, const int* in_sizes, int n_in,
                              void* d_out, int out_size)
{
    const float* x       = (const float*)d_in[0];
    const float* w_qkv   = (const float*)d_in[1];
    const float* w_out   = (const float*)d_in[2];
    const float* rel_emb = (const float*)d_in[3];
    const int*   rel_idx = (const int*)d_in[4];
    float* out = (float*)d_out;

    __half *x16, *wq16, *wo16, *qkv, *att;
    float* biasP;
    cudaGetSymbolAddress((void**)&x16,  g_x16);
    cudaGetSymbolAddress((void**)&wq16, g_wq16);
    cudaGetSymbolAddress((void**)&wo16, g_wo16);
    cudaGetSymbolAddress((void**)&qkv,  g_qkv);
    cudaGetSymbolAddress((void**)&att,  g_att);
    cudaGetSymbolAddress((void**)&biasP, g_biasP);

    cudaFuncSetAttribute(gemm_h_kernel<1>,
                         cudaFuncAttributeMaxDynamicSharedMemorySize, GSMEM);
    cudaFuncSetAttribute(gemm_h_kernel<0>,
                         cudaFuncAttributeMaxDynamicSharedMemorySize, GSMEM);

    int n4x = TTOT * DIM / 4;
    cvt_h_kernel<<<(n4x + 255) / 256, 256>>>((const float4*)x, (uint2*)x16, n4x);
    {
        int tot = QKV_E * DIM / 4 + DIM * DIM / 4 + HEADS * 64 * 64;
        prep_small_kernel<<<(tot + 255) / 256, 256>>>(
            (const float4*)w_qkv, (const float4*)w_out, rel_emb, rel_idx,
            (uint2*)wq16, (uint2*)wo16, biasP);
    }

    // 1) qkv = x @ w_qkv^T   (A-resident GEMM, 6 n-tiles)
    gemm_h_kernel<1><<<TTOT / 128, 256, GSMEM>>>(x16, wq16, qkv, QKV_E);

    // 2) windowed attention (one (win,head) per 128-thread block)
    attn_kernel<<<WINS * HEADS, 128>>>(qkv, biasP, att);

    // 3) out = att @ w_out^T (A-resident GEMM, 2 n-tiles)
    gemm_h_kernel<0><<<TTOT / 128, 256, GSMEM>>>(att, wo16, out, DIM);
}

// round 10
// speedup vs baseline: 1.3089x; 1.0740x over previous
#include <cuda_runtime.h>
#include <cuda_fp16.h>
#include <cstdint>

#define WINS   4096
#define NTOK   49
#define DIM    256
#define HEADS  8
#define DH     32
#define TTOT   (WINS * NTOK)      // 200704
#define QKV_E  768
#define SCALE  0.17677669529663687f

// ------------------------- scratch (device globals) -------------------------
__device__ __half g_wq16[QKV_E * DIM];
__device__ __half g_wo16[DIM * DIM];
__device__ __half g_qkv [(size_t)TTOT * QKV_E];   // 308 MB
__device__ __half g_att [(size_t)TTOT * DIM];     // 103 MB
__device__ __half g_bias16[HEADS * 64 * 64];      // padded bias (fp16)

// ------------------------------ helpers ------------------------------------
__device__ __forceinline__ uint32_t smem_u32(const void* p) {
    uint32_t a;
    asm("{ .reg .u64 t; cvta.to.shared.u64 t, %1; cvt.u32.u64 %0, t; }"
        : "=r"(a) : "l"(p));
    return a;
}
__device__ __forceinline__ void cp16(uint32_t dst, const void* src) {
    asm volatile("cp.async.cg.shared.global [%0], [%1], 16;\n" :: "r"(dst), "l"(src));
}
__device__ __forceinline__ void cp_commit() {
    asm volatile("cp.async.commit_group;\n" ::);
}
template <int N> __device__ __forceinline__ void cp_wait() {
    asm volatile("cp.async.wait_group %0;\n" :: "n"(N) : "memory");
}
__device__ __forceinline__ void ldsm4(uint32_t& r0, uint32_t& r1, uint32_t& r2,
                                      uint32_t& r3, uint32_t a) {
    asm volatile("ldmatrix.sync.aligned.m8n8.x4.shared.b16 {%0,%1,%2,%3}, [%4];"
                 : "=r"(r0), "=r"(r1), "=r"(r2), "=r"(r3) : "r"(a) : "memory");
}
__device__ __forceinline__ void ldsm4t(uint32_t& r0, uint32_t& r1, uint32_t& r2,
                                       uint32_t& r3, uint32_t a) {
    asm volatile("ldmatrix.sync.aligned.m8n8.x4.trans.shared.b16 {%0,%1,%2,%3}, [%4];"
                 : "=r"(r0), "=r"(r1), "=r"(r2), "=r"(r3) : "r"(a) : "memory");
}
__device__ __forceinline__ void mma16816(float* d, uint32_t a0, uint32_t a1,
                                         uint32_t a2, uint32_t a3,
                                         uint32_t b0, uint32_t b1) {
    asm volatile(
        "mma.sync.aligned.m16n8k16.row.col.f32.f16.f16.f32 "
        "{%0,%1,%2,%3}, {%4,%5,%6,%7}, {%8,%9}, {%0,%1,%2,%3};"
        : "+f"(d[0]), "+f"(d[1]), "+f"(d[2]), "+f"(d[3])
        : "r"(a0), "r"(a1), "r"(a2), "r"(a3), "r"(b0), "r"(b1));
}
__device__ __forceinline__ uint32_t f22h2(float lo, float hi) {
    uint32_t r;
    asm("cvt.rn.f16x2.f32 %0, %1, %2;" : "=r"(r) : "f"(hi), "f"(lo));
    return r;
}

// ---------------------- GEMM (fp16 mma, A-resident) --------------------------
// C[M,N] = A[M,256]@B[N,256]^T. CTA owns 128 A-rows (full slab in smem), loops
// n-tiles streaming B (L2-resident) through a 3-stage cp.async pipeline.
// A_FP32: A is fp32 in gmem; convert to fp16 during the slab load.
#define SAROW 528                   // bytes per sA row (256 halfs + 16B pad)
#define SA_BYTES (128 * SAROW)      // 67584
#define BGROW 80                    // bytes per sB row
#define BST  (128 * BGROW)          // 10240 per stage
#define NSTG 3
#define GSMEM (SA_BYTES + NSTG * BST)   // 98304

template <int HALF_OUT, int A_FP32>
__global__ void __launch_bounds__(256, 2) gemm_h_kernel(
    const void* __restrict__ Av, const __half* __restrict__ B,
    void* __restrict__ Cv, int N)
{
    extern __shared__ char smem[];
    const uint32_t sA = smem_u32(smem);
    const uint32_t sB = sA + SA_BYTES;

    const int tid = threadIdx.x, lane = tid & 31, wid = tid >> 5;
    const int wm = wid & 1, wn = wid >> 1;
    const int bm = blockIdx.x * 128;
    const int ntiles = N >> 7;
    const int NQ = ntiles * 8;

    // ---- B stage loader: stream index q = nt*8 + ks ----
    const int b_row = tid >> 1;
    auto ld_B = [&](int q, int buf) {
        const int nt = q >> 3, ks = q & 7;
        const __half* src = B + (size_t)(nt * 128 + b_row) * DIM + ks * 32;
#pragma unroll
        for (int h = 0; h < 2; h++) {
            int ch = (tid & 1) + h * 2;
            cp16(sB + buf * BST + b_row * BGROW + ch * 16, src + ch * 8);
        }
        cp_commit();
    };

    // ---- load full A slab (128 x 256 halfs) ----
    if (A_FP32) {
        // start B first so its latency overlaps the A convert loop
        ld_B(0, 0);
        ld_B(1, 1);
        const float* Af = (const float*)Av;
#pragma unroll
        for (int it = 0; it < 16; it++) {
            int idx = tid + it * 256;
            int row = idx >> 5, ch = idx & 31;
            const float* src = Af + (size_t)(bm + row) * DIM + ch * 8;
            float4 v0 = *(const float4*)src;
            float4 v1 = *(const float4*)(src + 4);
            uint4 h = make_uint4(f22h2(v0.x, v0.y), f22h2(v0.z, v0.w),
                                 f22h2(v1.x, v1.y), f22h2(v1.z, v1.w));
            *(uint4*)(smem + row * SAROW + ch * 16) = h;
        }
    } else {
        const __half* Ah = (const __half*)Av;
#pragma unroll
        for (int it = 0; it < 16; it++) {
            int idx = tid + it * 256;
            int row = idx >> 5, ch = idx & 31;
            cp16(sA + row * SAROW + ch * 16,
                 Ah + (size_t)(bm + row) * DIM + ch * 8);
        }
        cp_commit();
        ld_B(0, 0);
        ld_B(1, 1);
    }

    const int l7 = lane & 7;
    const uint32_t aBase = sA + (wm * 64 + l7 + ((lane >> 3) & 1) * 8) * SAROW
                              + (lane >> 4) * 16;
    const uint32_t bBase = sB + (wn * 32 + (lane >> 4) * 8 + l7) * BGROW
                              + ((lane >> 3) & 1) * 16;

    const int r = lane >> 2, c = lane & 3;

    for (int nt = 0; nt < ntiles; nt++) {
        float acc[4][4][4];
#pragma unroll
        for (int mt = 0; mt < 4; mt++)
#pragma unroll
            for (int ntt = 0; ntt < 4; ntt++)
#pragma unroll
                for (int i = 0; i < 4; i++) acc[mt][ntt][i] = 0.f;

#pragma unroll
        for (int ks = 0; ks < 8; ks++) {
            const int q = nt * 8 + ks;
            if (q + 1 < NQ) cp_wait<1>(); else cp_wait<0>();
            __syncthreads();
            const uint32_t bcur = bBase + (q % NSTG) * BST;

#pragma unroll
            for (int kt = 0; kt < 2; kt++) {
                uint32_t af[4][4], bf[4][2];
#pragma unroll
                for (int mt = 0; mt < 4; mt++)
                    ldsm4(af[mt][0], af[mt][1], af[mt][2], af[mt][3],
                          aBase + mt * 16 * SAROW + ks * 64 + kt * 32);
#pragma unroll
                for (int p = 0; p < 2; p++)
                    ldsm4(bf[2 * p][0], bf[2 * p][1], bf[2 * p + 1][0], bf[2 * p + 1][1],
                          bcur + p * 16 * BGROW + kt * 32);
#pragma unroll
                for (int mt = 0; mt < 4; mt++)
#pragma unroll
                    for (int ntt = 0; ntt < 4; ntt++)
                        mma16816(acc[mt][ntt], af[mt][0], af[mt][1], af[mt][2], af[mt][3],
                                 bf[ntt][0], bf[ntt][1]);
            }
            __syncthreads();
            if (q + 2 < NQ) ld_B(q + 2, (q + 2) % NSTG);
        }

        const int bn = nt * 128;
#pragma unroll
        for (int mt = 0; mt < 4; mt++) {
            const int row = bm + wm * 64 + mt * 16 + r;
#pragma unroll
            for (int ntt = 0; ntt < 4; ntt++) {
                const int col = bn + wn * 32 + ntt * 8 + 2 * c;
                if (HALF_OUT) {
                    __half* C = (__half*)Cv;
                    *(uint32_t*)&C[(size_t)row * N + col] =
                        f22h2(acc[mt][ntt][0], acc[mt][ntt][1]);
                    *(uint32_t*)&C[(size_t)(row + 8) * N + col] =
                        f22h2(acc[mt][ntt][2], acc[mt][ntt][3]);
                } else {
                    float* C = (float*)Cv;
                    *(float2*)&C[(size_t)row * N + col] =
                        make_float2(acc[mt][ntt][0], acc[mt][ntt][1]);
                    *(float2*)&C[(size_t)(row + 8) * N + col] =
                        make_float2(acc[mt][ntt][2], acc[mt][ntt][3]);
                }
            }
        }
    }
}

// --------------------------- attention (fp16 mma) ---------------------------
#define AROW 40                         // halfs per smem row (80B)

__global__ void __launch_bounds__(128, 5) attn_kernel(
    const __half* __restrict__ qkv, const __half* __restrict__ bias16,
    __half* __restrict__ att)
{
    __shared__ __half q[64 * AROW];
    __shared__ __half k[64 * AROW];
    __shared__ __half v[64 * AROW];

    const int tid  = threadIdx.x;
    const int lane = tid & 31;
    const int w    = tid >> 5;
    const int win  = blockIdx.x >> 3, head = blockIdx.x & 7;

    // zero pad rows 49..63
    {
        int rc = tid & 63;
        if (rc < 60) {
            int row = 49 + (rc >> 2), ch = rc & 3;
            __half* base = (tid < 64) ? q : k;
            *(uint4*)&base[row * AROW + ch * 8] = make_uint4(0, 0, 0, 0);
            if (tid < 64)
                *(uint4*)&v[row * AROW + ch * 8] = make_uint4(0, 0, 0, 0);
        }
    }
    // load q,k,v rows 0..48
    const __half* gbase = qkv + (size_t)win * NTOK * QKV_E + head * DH;
#pragma unroll
    for (int m = 0; m < 3; m++) {
        __half* base = (m == 0 ? q : (m == 1 ? k : v));
        const __half* gsrc = gbase + m * DIM;
#pragma unroll
        for (int it = 0; it < 2; it++) {
            int u = tid + it * 128;
            if (u < 196) {
                int row = u >> 2, ch = u & 3;
                cp16(smem_u32(&base[row * AROW + ch * 8]),
                     gsrc + (size_t)row * QKV_E + ch * 8);
            }
        }
    }
    cp_commit();
    cp_wait<0>();
    __syncthreads();

    const int l7 = lane & 7;
    const int wr = w * 16;
    const uint32_t qA = smem_u32(&q[(wr + l7 + ((lane >> 3) & 1) * 8) * AROW
                                    + (lane >> 4) * 8]);
    const uint32_t kB = smem_u32(&k[((lane >> 4) * 8 + l7) * AROW
                                    + ((lane >> 3) & 1) * 8]);
    const uint32_t vB = smem_u32(&v[(l7 + ((lane >> 3) & 1) * 8) * AROW
                                    + (lane >> 4) * 8]);

    float s[8][4];
#pragma unroll
    for (int nt = 0; nt < 8; nt++)
#pragma unroll
        for (int i = 0; i < 4; i++) s[nt][i] = 0.f;

#pragma unroll
    for (int kt = 0; kt < 2; kt++) {
        uint32_t a0, a1, a2, a3;
        ldsm4(a0, a1, a2, a3, qA + kt * 32);
#pragma unroll
        for (int p = 0; p < 4; p++) {
            uint32_t b0, b1, b2, b3;
            ldsm4(b0, b1, b2, b3, kB + p * 16 * AROW * 2 + kt * 32);
            mma16816(s[2 * p],     a0, a1, a2, a3, b0, b1);
            mma16816(s[2 * p + 1], a0, a1, a2, a3, b2, b3);
        }
    }

    const int r = lane >> 2, c = lane & 3;
    const __half* bp = bias16 + head * 4096;
#pragma unroll
    for (int nt = 0; nt < 8; nt++) {
        uint32_t u0 = *(const uint32_t*)&bp[(wr + r) * 64 + nt * 8 + 2 * c];
        uint32_t u1 = *(const uint32_t*)&bp[(wr + r + 8) * 64 + nt * 8 + 2 * c];
        float2 b0 = __half22float2(*(__half2*)&u0);
        float2 b1 = __half22float2(*(__half2*)&u1);
        s[nt][0] = fmaf(s[nt][0], SCALE, b0.x);
        s[nt][1] = fmaf(s[nt][1], SCALE, b0.y);
        s[nt][2] = fmaf(s[nt][2], SCALE, b1.x);
        s[nt][3] = fmaf(s[nt][3], SCALE, b1.y);
    }
    float m0 = -1e30f, m1 = -1e30f;
#pragma unroll
    for (int nt = 0; nt < 8; nt++) {
        m0 = fmaxf(m0, fmaxf(s[nt][0], s[nt][1]));
        m1 = fmaxf(m1, fmaxf(s[nt][2], s[nt][3]));
    }
    m0 = fmaxf(m0, __shfl_xor_sync(0xffffffffu, m0, 1));
    m0 = fmaxf(m0, __shfl_xor_sync(0xffffffffu, m0, 2));
    m1 = fmaxf(m1, __shfl_xor_sync(0xffffffffu, m1, 1));
    m1 = fmaxf(m1, __shfl_xor_sync(0xffffffffu, m1, 2));
    float sum0 = 0.f, sum1 = 0.f;
#pragma unroll
    for (int nt = 0; nt < 8; nt++) {
        s[nt][0] = __expf(s[nt][0] - m0);
        s[nt][1] = __expf(s[nt][1] - m0);
        s[nt][2] = __expf(s[nt][2] - m1);
        s[nt][3] = __expf(s[nt][3] - m1);
        sum0 += s[nt][0] + s[nt][1];
        sum1 += s[nt][2] + s[nt][3];
    }
    sum0 += __shfl_xor_sync(0xffffffffu, sum0, 1);
    sum0 += __shfl_xor_sync(0xffffffffu, sum0, 2);
    sum1 += __shfl_xor_sync(0xffffffffu, sum1, 1);
    sum1 += __shfl_xor_sync(0xffffffffu, sum1, 2);
    const float inv0 = 1.f / sum0, inv1 = 1.f / sum1;

    uint32_t pf[4][4];
#pragma unroll
    for (int kt = 0; kt < 4; kt++) {
        pf[kt][0] = f22h2(s[2 * kt][0],     s[2 * kt][1]);
        pf[kt][1] = f22h2(s[2 * kt][2],     s[2 * kt][3]);
        pf[kt][2] = f22h2(s[2 * kt + 1][0], s[2 * kt + 1][1]);
        pf[kt][3] = f22h2(s[2 * kt + 1][2], s[2 * kt + 1][3]);
    }

    float o[4][4];
#pragma unroll
    for (int nb = 0; nb < 4; nb++)
#pragma unroll
        for (int i = 0; i < 4; i++) o[nb][i] = 0.f;
#pragma unroll
    for (int kt = 0; kt < 4; kt++) {
#pragma unroll
        for (int p = 0; p < 2; p++) {
            uint32_t b0, b1, b2, b3;
            ldsm4t(b0, b1, b2, b3, vB + kt * 16 * AROW * 2 + p * 32);
            mma16816(o[2 * p],     pf[kt][0], pf[kt][1], pf[kt][2], pf[kt][3], b0, b1);
            mma16816(o[2 * p + 1], pf[kt][0], pf[kt][1], pf[kt][2], pf[kt][3], b2, b3);
        }
    }

    const int row0 = wr + r, row1 = wr + r + 8;
#pragma unroll
    for (int nb = 0; nb < 4; nb++) {
        const int col = head * DH + nb * 8 + 2 * c;
        if (row0 < NTOK)
            *(uint32_t*)&att[((size_t)win * NTOK + row0) * DIM + col] =
                f22h2(o[nb][0] * inv0, o[nb][1] * inv0);
        if (row1 < NTOK)
            *(uint32_t*)&att[((size_t)win * NTOK + row1) * DIM + col] =
                f22h2(o[nb][2] * inv1, o[nb][3] * inv1);
    }
}

// ------------------------------ prep kernel ---------------------------------
__global__ void prep_small_kernel(const float4* __restrict__ wq,
                                  const float4* __restrict__ wo,
                                  const float*  __restrict__ rel_emb,
                                  const int*    __restrict__ rel_idx,
                                  uint2* __restrict__ wq16,
                                  uint2* __restrict__ wo16,
                                  __half* __restrict__ bias16)
{
    const int NWQ = QKV_E * DIM / 4;
    const int NWO = DIM * DIM / 4;
    const int NB  = HEADS * 64 * 64;
    int i = blockIdx.x * 256 + threadIdx.x;
    if (i < NWQ) {
        float4 v = wq[i];
        wq16[i] = make_uint2(f22h2(v.x, v.y), f22h2(v.z, v.w));
    } else if (i < NWQ + NWO) {
        int j = i - NWQ;
        float4 v = wo[j];
        wo16[j] = make_uint2(f22h2(v.x, v.y), f22h2(v.z, v.w));
    } else if (i < NWQ + NWO + NB) {
        int e = i - NWQ - NWO;
        int h = e >> 12, rc = e & 4095, rr = rc >> 6, cc = rc & 63;
        float bv = (rr < NTOK && cc < NTOK)
                 ? rel_emb[rel_idx[rr * NTOK + cc] * HEADS + h] : -60000.f;
        bias16[e] = __float2half(bv);
    }
}

// ----------------------------------------------------------------------------
extern "C" void kernel_launch(void* const* d_in, const int* in_sizes, int n_in,
                              void* d_out, int out_size)
{
    const float* x       = (const float*)d_in[0];
    const float* w_qkv   = (const float*)d_in[1];
    const float* w_out   = (const float*)d_in[2];
    const float* rel_emb = (const float*)d_in[3];
    const int*   rel_idx = (const int*)d_in[4];
    float* out = (float*)d_out;

    __half *wq16, *wo16, *qkv, *att, *bias16;
    cudaGetSymbolAddress((void**)&wq16, g_wq16);
    cudaGetSymbolAddress((void**)&wo16, g_wo16);
    cudaGetSymbolAddress((void**)&qkv,  g_qkv);
    cudaGetSymbolAddress((void**)&att,  g_att);
    cudaGetSymbolAddress((void**)&bias16, g_bias16);

    cudaFuncSetAttribute((void*)gemm_h_kernel<1, 1>,
                         cudaFuncAttributeMaxDynamicSharedMemorySize, GSMEM);
    cudaFuncSetAttribute((void*)gemm_h_kernel<0, 0>,
                         cudaFuncAttributeMaxDynamicSharedMemorySize, GSMEM);

    {
        int tot = QKV_E * DIM / 4 + DIM * DIM / 4 + HEADS * 64 * 64;
        prep_small_kernel<<<(tot + 255) / 256, 256>>>(
            (const float4*)w_qkv, (const float4*)w_out, rel_emb, rel_idx,
            (uint2*)wq16, (uint2*)wo16, bias16);
    }

    // 1) qkv = x @ w_qkv^T   (A fp32->fp16 conversion fused into slab load)
    gemm_h_kernel<1, 1><<<TTOT / 128, 256, GSMEM>>>(x, wq16, qkv, QKV_E);

    // 2) windowed attention
    attn_kernel<<<WINS * HEADS, 128>>>(qkv, bias16, att);

    // 3) out = att @ w_out^T
    gemm_h_kernel<0, 0><<<TTOT / 128, 256, GSMEM>>>(att, wo16, out, DIM);
}

// round 11
// speedup vs baseline: 1.3902x; 1.0621x over previous
#include <cuda_runtime.h>
#include <cuda_fp16.h>
#include <cstdint>

#define WINS   4096
#define NTOK   49
#define DIM    256
#define HEADS  8
#define DH     32
#define TTOT   (WINS * NTOK)      // 200704
#define QKV_E  768
#define SCALE  0.17677669529663687f

// ------------------------- scratch (device globals) -------------------------
__device__ __half g_wq16[QKV_E * DIM];
__device__ __half g_wo16[DIM * DIM];
__device__ __half g_qkv [(size_t)TTOT * QKV_E];   // 308 MB
__device__ __half g_att [(size_t)TTOT * DIM];     // 103 MB
__device__ __half g_bias16[HEADS * 64 * 64];      // padded bias (fp16)

// ------------------------------ helpers ------------------------------------
__device__ __forceinline__ uint32_t smem_u32(const void* p) {
    uint32_t a;
    asm("{ .reg .u64 t; cvta.to.shared.u64 t, %1; cvt.u32.u64 %0, t; }"
        : "=r"(a) : "l"(p));
    return a;
}
__device__ __forceinline__ void cp16(uint32_t dst, const void* src) {
    asm volatile("cp.async.cg.shared.global [%0], [%1], 16;\n" :: "r"(dst), "l"(src));
}
__device__ __forceinline__ void cp_commit() {
    asm volatile("cp.async.commit_group;\n" ::);
}
template <int N> __device__ __forceinline__ void cp_wait() {
    asm volatile("cp.async.wait_group %0;\n" :: "n"(N) : "memory");
}
__device__ __forceinline__ void ldsm4(uint32_t& r0, uint32_t& r1, uint32_t& r2,
                                      uint32_t& r3, uint32_t a) {
    asm volatile("ldmatrix.sync.aligned.m8n8.x4.shared.b16 {%0,%1,%2,%3}, [%4];"
                 : "=r"(r0), "=r"(r1), "=r"(r2), "=r"(r3) : "r"(a) : "memory");
}
__device__ __forceinline__ void ldsm4t(uint32_t& r0, uint32_t& r1, uint32_t& r2,
                                       uint32_t& r3, uint32_t a) {
    asm volatile("ldmatrix.sync.aligned.m8n8.x4.trans.shared.b16 {%0,%1,%2,%3}, [%4];"
                 : "=r"(r0), "=r"(r1), "=r"(r2), "=r"(r3) : "r"(a) : "memory");
}
__device__ __forceinline__ void mma16816(float* d, uint32_t a0, uint32_t a1,
                                         uint32_t a2, uint32_t a3,
                                         uint32_t b0, uint32_t b1) {
    asm volatile(
        "mma.sync.aligned.m16n8k16.row.col.f32.f16.f16.f32 "
        "{%0,%1,%2,%3}, {%4,%5,%6,%7}, {%8,%9}, {%0,%1,%2,%3};"
        : "+f"(d[0]), "+f"(d[1]), "+f"(d[2]), "+f"(d[3])
        : "r"(a0), "r"(a1), "r"(a2), "r"(a3), "r"(b0), "r"(b1));
}
__device__ __forceinline__ uint32_t f22h2(float lo, float hi) {
    uint32_t r;
    asm("cvt.rn.f16x2.f32 %0, %1, %2;" : "=r"(r) : "f"(hi), "f"(lo));
    return r;
}

// ---------------------- GEMM (fp16 mma, A-resident) --------------------------
// C[M,N] = A[M,256]@B[N,256]^T. CTA owns 128 A-rows (full slab in smem), loops
// n-tiles streaming B (L2-resident) through a 4-stage cp.async pipeline with
// ONE barrier per K-step and prefetch depth 3.
#define SAROW 528                   // bytes per sA row (256 halfs + 16B pad)
#define SA_BYTES (128 * SAROW)      // 67584
#define BGROW 80                    // bytes per sB row
#define BST  (128 * BGROW)          // 10240 per stage
#define NSTG 4
#define GSMEM (SA_BYTES + NSTG * BST)   // 108544

template <int HALF_OUT, int A_FP32>
__global__ void __launch_bounds__(256, 2) gemm_h_kernel(
    const void* __restrict__ Av, const __half* __restrict__ B,
    void* __restrict__ Cv, int N)
{
    extern __shared__ char smem[];
    const uint32_t sA = smem_u32(smem);
    const uint32_t sB = sA + SA_BYTES;

    const int tid = threadIdx.x, lane = tid & 31, wid = tid >> 5;
    const int wm = wid & 1, wn = wid >> 1;
    const int bm = blockIdx.x * 128;
    const int ntiles = N >> 7;
    const int NQ = ntiles * 8;

    // ---- B stage loader: stream index q = nt*8 + ks ----
    const int b_row = tid >> 1;
    auto ld_B = [&](int q, int buf) {
        const int nt = q >> 3, ks = q & 7;
        const __half* src = B + (size_t)(nt * 128 + b_row) * DIM + ks * 32;
#pragma unroll
        for (int h = 0; h < 2; h++) {
            int ch = (tid & 1) + h * 2;
            cp16(sB + buf * BST + b_row * BGROW + ch * 16, src + ch * 8);
        }
        cp_commit();
    };

    // ---- load full A slab (128 x 256 halfs) ----
    if (A_FP32) {
        ld_B(0, 0);
        ld_B(1, 1);
        ld_B(2, 2);
        const float* Af = (const float*)Av;
#pragma unroll
        for (int it = 0; it < 16; it++) {
            int idx = tid + it * 256;
            int row = idx >> 5, ch = idx & 31;
            const float* src = Af + (size_t)(bm + row) * DIM + ch * 8;
            float4 v0 = *(const float4*)src;
            float4 v1 = *(const float4*)(src + 4);
            uint4 h = make_uint4(f22h2(v0.x, v0.y), f22h2(v0.z, v0.w),
                                 f22h2(v1.x, v1.y), f22h2(v1.z, v1.w));
            *(uint4*)(smem + row * SAROW + ch * 16) = h;
        }
    } else {
        const __half* Ah = (const __half*)Av;
#pragma unroll
        for (int it = 0; it < 16; it++) {
            int idx = tid + it * 256;
            int row = idx >> 5, ch = idx & 31;
            cp16(sA + row * SAROW + ch * 16,
                 Ah + (size_t)(bm + row) * DIM + ch * 8);
        }
        cp_commit();
        ld_B(0, 0);
        ld_B(1, 1);
        ld_B(2, 2);
    }

    const int l7 = lane & 7;
    const uint32_t aBase = sA + (wm * 64 + l7 + ((lane >> 3) & 1) * 8) * SAROW
                              + (lane >> 4) * 16;
    const uint32_t bBase = sB + (wn * 32 + (lane >> 4) * 8 + l7) * BGROW
                              + ((lane >> 3) & 1) * 16;

    const int r = lane >> 2, c = lane & 3;

    for (int nt = 0; nt < ntiles; nt++) {
        float acc[4][4][4];
#pragma unroll
        for (int mt = 0; mt < 4; mt++)
#pragma unroll
            for (int ntt = 0; ntt < 4; ntt++)
#pragma unroll
                for (int i = 0; i < 4; i++) acc[mt][ntt][i] = 0.f;

#pragma unroll
        for (int ks = 0; ks < 8; ks++) {
            const int q = nt * 8 + ks;
            const int rem = NQ - 1 - q;
            if (rem >= 2) cp_wait<2>(); else if (rem == 1) cp_wait<1>(); else cp_wait<0>();
            __syncthreads();              // single barrier per K-step
            const uint32_t bcur = bBase + (q & 3) * BST;

#pragma unroll
            for (int kt = 0; kt < 2; kt++) {
                uint32_t af[4][4], bf[4][2];
#pragma unroll
                for (int mt = 0; mt < 4; mt++)
                    ldsm4(af[mt][0], af[mt][1], af[mt][2], af[mt][3],
                          aBase + mt * 16 * SAROW + ks * 64 + kt * 32);
#pragma unroll
                for (int p = 0; p < 2; p++)
                    ldsm4(bf[2 * p][0], bf[2 * p][1], bf[2 * p + 1][0], bf[2 * p + 1][1],
                          bcur + p * 16 * BGROW + kt * 32);
#pragma unroll
                for (int mt = 0; mt < 4; mt++)
#pragma unroll
                    for (int ntt = 0; ntt < 4; ntt++)
                        mma16816(acc[mt][ntt], af[mt][0], af[mt][1], af[mt][2], af[mt][3],
                                 bf[ntt][0], bf[ntt][1]);
            }
            // prefetch 3 ahead into stage (q+3)&3 — distinct from stage q (being
            // read) and stages q+1,q+2 (fills in flight); start-of-step barrier
            // already fenced all reads of this stage from step q-1.
            if (q + 3 < NQ) ld_B(q + 3, (q + 3) & 3);
        }

        const int bn = nt * 128;
#pragma unroll
        for (int mt = 0; mt < 4; mt++) {
            const int row = bm + wm * 64 + mt * 16 + r;
#pragma unroll
            for (int ntt = 0; ntt < 4; ntt++) {
                const int col = bn + wn * 32 + ntt * 8 + 2 * c;
                if (HALF_OUT) {
                    __half* C = (__half*)Cv;
                    *(uint32_t*)&C[(size_t)row * N + col] =
                        f22h2(acc[mt][ntt][0], acc[mt][ntt][1]);
                    *(uint32_t*)&C[(size_t)(row + 8) * N + col] =
                        f22h2(acc[mt][ntt][2], acc[mt][ntt][3]);
                } else {
                    float* C = (float*)Cv;
                    *(float2*)&C[(size_t)row * N + col] =
                        make_float2(acc[mt][ntt][0], acc[mt][ntt][1]);
                    *(float2*)&C[(size_t)(row + 8) * N + col] =
                        make_float2(acc[mt][ntt][2], acc[mt][ntt][3]);
                }
            }
        }
        // NOTE: no barrier needed between n-tiles: next iteration's first
        // cp_wait + __syncthreads covers the epilogue (acc regs, no smem).
    }
}

// --------------------------- attention (fp16 mma) ---------------------------
#define AROW 40                         // halfs per smem row (80B)

__global__ void __launch_bounds__(128, 5) attn_kernel(
    const __half* __restrict__ qkv, const __half* __restrict__ bias16,
    __half* __restrict__ att)
{
    __shared__ __half q[64 * AROW];
    __shared__ __half k[64 * AROW];
    __shared__ __half v[64 * AROW];

    const int tid  = threadIdx.x;
    const int lane = tid & 31;
    const int w    = tid >> 5;
    const int win  = blockIdx.x >> 3, head = blockIdx.x & 7;

    // zero pad rows 49..63
    {
        int rc = tid & 63;
        if (rc < 60) {
            int row = 49 + (rc >> 2), ch = rc & 3;
            __half* base = (tid < 64) ? q : k;
            *(uint4*)&base[row * AROW + ch * 8] = make_uint4(0, 0, 0, 0);
            if (tid < 64)
                *(uint4*)&v[row * AROW + ch * 8] = make_uint4(0, 0, 0, 0);
        }
    }
    // load q,k,v rows 0..48
    const __half* gbase = qkv + (size_t)win * NTOK * QKV_E + head * DH;
#pragma unroll
    for (int m = 0; m < 3; m++) {
        __half* base = (m == 0 ? q : (m == 1 ? k : v));
        const __half* gsrc = gbase + m * DIM;
#pragma unroll
        for (int it = 0; it < 2; it++) {
            int u = tid + it * 128;
            if (u < 196) {
                int row = u >> 2, ch = u & 3;
                cp16(smem_u32(&base[row * AROW + ch * 8]),
                     gsrc + (size_t)row * QKV_E + ch * 8);
            }
        }
    }
    cp_commit();
    cp_wait<0>();
    __syncthreads();

    const int l7 = lane & 7;
    const int wr = w * 16;
    const uint32_t qA = smem_u32(&q[(wr + l7 + ((lane >> 3) & 1) * 8) * AROW
                                    + (lane >> 4) * 8]);
    const uint32_t kB = smem_u32(&k[((lane >> 4) * 8 + l7) * AROW
                                    + ((lane >> 3) & 1) * 8]);
    const uint32_t vB = smem_u32(&v[(l7 + ((lane >> 3) & 1) * 8) * AROW
                                    + (lane >> 4) * 8]);

    float s[8][4];
#pragma unroll
    for (int nt = 0; nt < 8; nt++)
#pragma unroll
        for (int i = 0; i < 4; i++) s[nt][i] = 0.f;

#pragma unroll
    for (int kt = 0; kt < 2; kt++) {
        uint32_t a0, a1, a2, a3;
        ldsm4(a0, a1, a2, a3, qA + kt * 32);
#pragma unroll
        for (int p = 0; p < 4; p++) {
            uint32_t b0, b1, b2, b3;
            ldsm4(b0, b1, b2, b3, kB + p * 16 * AROW * 2 + kt * 32);
            mma16816(s[2 * p],     a0, a1, a2, a3, b0, b1);
            mma16816(s[2 * p + 1], a0, a1, a2, a3, b2, b3);
        }
    }

    const int r = lane >> 2, c = lane & 3;
    const __half* bp = bias16 + head * 4096;
#pragma unroll
    for (int nt = 0; nt < 8; nt++) {
        uint32_t u0 = *(const uint32_t*)&bp[(wr + r) * 64 + nt * 8 + 2 * c];
        uint32_t u1 = *(const uint32_t*)&bp[(wr + r + 8) * 64 + nt * 8 + 2 * c];
        float2 b0 = __half22float2(*(__half2*)&u0);
        float2 b1 = __half22float2(*(__half2*)&u1);
        s[nt][0] = fmaf(s[nt][0], SCALE, b0.x);
        s[nt][1] = fmaf(s[nt][1], SCALE, b0.y);
        s[nt][2] = fmaf(s[nt][2], SCALE, b1.x);
        s[nt][3] = fmaf(s[nt][3], SCALE, b1.y);
    }
    float m0 = -1e30f, m1 = -1e30f;
#pragma unroll
    for (int nt = 0; nt < 8; nt++) {
        m0 = fmaxf(m0, fmaxf(s[nt][0], s[nt][1]));
        m1 = fmaxf(m1, fmaxf(s[nt][2], s[nt][3]));
    }
    m0 = fmaxf(m0, __shfl_xor_sync(0xffffffffu, m0, 1));
    m0 = fmaxf(m0, __shfl_xor_sync(0xffffffffu, m0, 2));
    m1 = fmaxf(m1, __shfl_xor_sync(0xffffffffu, m1, 1));
    m1 = fmaxf(m1, __shfl_xor_sync(0xffffffffu, m1, 2));
    float sum0 = 0.f, sum1 = 0.f;
#pragma unroll
    for (int nt = 0; nt < 8; nt++) {
        s[nt][0] = __expf(s[nt][0] - m0);
        s[nt][1] = __expf(s[nt][1] - m0);
        s[nt][2] = __expf(s[nt][2] - m1);
        s[nt][3] = __expf(s[nt][3] - m1);
        sum0 += s[nt][0] + s[nt][1];
        sum1 += s[nt][2] + s[nt][3];
    }
    sum0 += __shfl_xor_sync(0xffffffffu, sum0, 1);
    sum0 += __shfl_xor_sync(0xffffffffu, sum0, 2);
    sum1 += __shfl_xor_sync(0xffffffffu, sum1, 1);
    sum1 += __shfl_xor_sync(0xffffffffu, sum1, 2);
    const float inv0 = 1.f / sum0, inv1 = 1.f / sum1;

    uint32_t pf[4][4];
#pragma unroll
    for (int kt = 0; kt < 4; kt++) {
        pf[kt][0] = f22h2(s[2 * kt][0],     s[2 * kt][1]);
        pf[kt][1] = f22h2(s[2 * kt][2],     s[2 * kt][3]);
        pf[kt][2] = f22h2(s[2 * kt + 1][0], s[2 * kt + 1][1]);
        pf[kt][3] = f22h2(s[2 * kt + 1][2], s[2 * kt + 1][3]);
    }

    float o[4][4];
#pragma unroll
    for (int nb = 0; nb < 4; nb++)
#pragma unroll
        for (int i = 0; i < 4; i++) o[nb][i] = 0.f;
#pragma unroll
    for (int kt = 0; kt < 4; kt++) {
#pragma unroll
        for (int p = 0; p < 2; p++) {
            uint32_t b0, b1, b2, b3;
            ldsm4t(b0, b1, b2, b3, vB + kt * 16 * AROW * 2 + p * 32);
            mma16816(o[2 * p],     pf[kt][0], pf[kt][1], pf[kt][2], pf[kt][3], b0, b1);
            mma16816(o[2 * p + 1], pf[kt][0], pf[kt][1], pf[kt][2], pf[kt][3], b2, b3);
        }
    }

    const int row0 = wr + r, row1 = wr + r + 8;
#pragma unroll
    for (int nb = 0; nb < 4; nb++) {
        const int col = head * DH + nb * 8 + 2 * c;
        if (row0 < NTOK)
            *(uint32_t*)&att[((size_t)win * NTOK + row0) * DIM + col] =
                f22h2(o[nb][0] * inv0, o[nb][1] * inv0);
        if (row1 < NTOK)
            *(uint32_t*)&att[((size_t)win * NTOK + row1) * DIM + col] =
                f22h2(o[nb][2] * inv1, o[nb][3] * inv1);
    }
}

// ------------------------------ prep kernel ---------------------------------
__global__ void prep_small_kernel(const float4* __restrict__ wq,
                                  const float4* __restrict__ wo,
                                  const float*  __restrict__ rel_emb,
                                  const int*    __restrict__ rel_idx,
                                  uint2* __restrict__ wq16,
                                  uint2* __restrict__ wo16,
                                  __half* __restrict__ bias16)
{
    const int NWQ = QKV_E * DIM / 4;
    const int NWO = DIM * DIM / 4;
    const int NB  = HEADS * 64 * 64;
    int i = blockIdx.x * 256 + threadIdx.x;
    if (i < NWQ) {
        float4 v = wq[i];
        wq16[i] = make_uint2(f22h2(v.x, v.y), f22h2(v.z, v.w));
    } else if (i < NWQ + NWO) {
        int j = i - NWQ;
        float4 v = wo[j];
        wo16[j] = make_uint2(f22h2(v.x, v.y), f22h2(v.z, v.w));
    } else if (i < NWQ + NWO + NB) {
        int e = i - NWQ - NWO;
        int h = e >> 12, rc = e & 4095, rr = rc >> 6, cc = rc & 63;
        float bv = (rr < NTOK && cc < NTOK)
                 ? rel_emb[rel_idx[rr * NTOK + cc] * HEADS + h] : -60000.f;
        bias16[e] = __float2half(bv);
    }
}

// ----------------------------------------------------------------------------
extern "C" void kernel_launch(void* const* d_in, const int* in_sizes, int n_in,
                              void* d_out, int out_size)
{
    const float* x       = (const float*)d_in[0];
    const float* w_qkv   = (const float*)d_in[1];
    const float* w_out   = (const float*)d_in[2];
    const float* rel_emb = (const float*)d_in[3];
    const int*   rel_idx = (const int*)d_in[4];
    float* out = (float*)d_out;

    __half *wq16, *wo16, *qkv, *att, *bias16;
    cudaGetSymbolAddress((void**)&wq16, g_wq16);
    cudaGetSymbolAddress((void**)&wo16, g_wo16);
    cudaGetSymbolAddress((void**)&qkv,  g_qkv);
    cudaGetSymbolAddress((void**)&att,  g_att);
    cudaGetSymbolAddress((void**)&bias16, g_bias16);

    cudaFuncSetAttribute((void*)gemm_h_kernel<1, 1>,
                         cudaFuncAttributeMaxDynamicSharedMemorySize, GSMEM);
    cudaFuncSetAttribute((void*)gemm_h_kernel<0, 0>,
                         cudaFuncAttributeMaxDynamicSharedMemorySize, GSMEM);

    {
        int tot = QKV_E * DIM / 4 + DIM * DIM / 4 + HEADS * 64 * 64;
        prep_small_kernel<<<(tot + 255) / 256, 256>>>(
            (const float4*)w_qkv, (const float4*)w_out, rel_emb, rel_idx,
            (uint2*)wq16, (uint2*)wo16, bias16);
    }

    // 1) qkv = x @ w_qkv^T   (A fp32->fp16 conversion fused into slab load)
    gemm_h_kernel<1, 1><<<TTOT / 128, 256, GSMEM>>>(x, wq16, qkv, QKV_E);

    // 2) windowed attention
    attn_kernel<<<WINS * HEADS, 128>>>(qkv, bias16, att);

    // 3) out = att @ w_out^T
    gemm_h_kernel<0, 0><<<TTOT / 128, 256, GSMEM>>>(att, wo16, out, DIM);
}